// round 10
// baseline (speedup 1.0000x reference)
#include <cuda_runtime.h>
#include <cuda_fp16.h>
#include <cstdint>

// Problem constants
#define B_    64
#define C_    100
#define NB_   150
#define FEAT_ 2052
#define OUT_  2048
#define M_    6400          // B_*C_
#define KP_   2112          // GEMM1 K padded
#define NCH_  65            // chunks of BK=32
#define CPAD_ 112           // per-image padded row count for support (K3 k-dim)
#define SROWS (B_ * CPAD_)  // 7168

// Scratch (static device arrays; no runtime allocation allowed)
__device__ __half g_A[(size_t)M_ * KP_];              // x in fp16
__device__ __half g_W[(size_t)OUT_ * KP_];            // K-major: [n][k]
__device__ __half g_S[(size_t)SROWS * OUT_];          // support fp16, rows b*112+c
__device__ __half g_adjh[(size_t)B_ * 128 * CPAD_];   // newadj hi [b][c(128)][n(112)]
__device__ __half g_adjl[(size_t)B_ * 128 * CPAD_];

// ---------------------------------------------------------------------------
__device__ __forceinline__ uint32_t smem_u32(const void* p) {
  uint32_t a;
  asm("{ .reg .u64 t; cvta.to.shared.u64 t, %1; cvt.u32.u64 %0, t; }" : "=r"(a) : "l"(p));
  return a;
}
__device__ __forceinline__ void cp_async16(uint32_t dst, const void* src) {
  asm volatile("cp.async.cg.shared.global [%0], [%1], 16;" :: "r"(dst), "l"(src));
}
__device__ __forceinline__ void ldm4(uint32_t* r, uint32_t addr) {
  asm volatile("ldmatrix.sync.aligned.m8n8.x4.shared.b16 {%0,%1,%2,%3}, [%4];"
               : "=r"(r[0]), "=r"(r[1]), "=r"(r[2]), "=r"(r[3]) : "r"(addr));
}
__device__ __forceinline__ void ldm4t(uint32_t* r, uint32_t addr) {
  asm volatile("ldmatrix.sync.aligned.m8n8.x4.trans.shared.b16 {%0,%1,%2,%3}, [%4];"
               : "=r"(r[0]), "=r"(r[1]), "=r"(r[2]), "=r"(r[3]) : "r"(addr));
}
__device__ __forceinline__ void mma_f16(float* c, const uint32_t* a, const uint32_t* b) {
  asm volatile("mma.sync.aligned.m16n8k16.row.col.f32.f16.f16.f32 "
               "{%0,%1,%2,%3}, {%4,%5,%6,%7}, {%8,%9}, {%0,%1,%2,%3};"
               : "+f"(c[0]), "+f"(c[1]), "+f"(c[2]), "+f"(c[3])
               : "r"(a[0]), "r"(a[1]), "r"(a[2]), "r"(a[3]), "r"(b[0]), "r"(b[1]));
}
__device__ __forceinline__ uint32_t packh2(__half a, __half b) {
  __half2 h = __halves2half2(a, b);
  return *(uint32_t*)&h;
}

// ---------------------------------------------------------------------------
// K1: build x[b,c,:] -> fp16, zero-pad to KP_. Slot search via SMEM labels.
// ---------------------------------------------------------------------------
__global__ __launch_bounds__(256) void build_x_kernel(
    const float* __restrict__ imgf, const float* __restrict__ bbox,
    const int* __restrict__ label, const int* __restrict__ batch,
    const float* __restrict__ lin_w, const float* __restrict__ lin_b) {
  int bc = blockIdx.x;
  int b = bc / C_, c = bc % C_;
  __shared__ int s_lab[NB_];
  __shared__ int s_idx[3];
  __shared__ float s_w[3];
  int t = threadIdx.x;
  if (t < 3) { s_idx[t] = -1; s_w[t] = 0.f; }
  if (t < NB_) {
    int i = b * NB_ + t;
    s_lab[t] = (batch[i] == b) ? label[i] : 0;
  }
  __syncthreads();
  if (t < NB_ && s_lab[t] == c + 1) {
    int slot = 0;
    for (int tp = 0; tp < t; tp++) slot += (s_lab[tp] == c + 1);
    if (slot < 3) { s_idx[slot] = b * NB_ + t; s_w[slot] = lin_w[slot]; }
  }
  __syncthreads();
  float lb = lin_b[0];
  int i0 = s_idx[0], i1 = s_idx[1], i2 = s_idx[2];
  float w0 = s_w[0], w1 = s_w[1], w2 = s_w[2];
  __half* hrow = g_A + (size_t)bc * KP_;
  for (int d4 = t; d4 < KP_ / 4; d4 += 256) {
    float4 acc = make_float4(0.f, 0.f, 0.f, 0.f);
    if (d4 < 512) {
      acc = make_float4(lb, lb, lb, lb);
      if (i0 >= 0) {
        float4 v = *(const float4*)(imgf + (size_t)i0 * 2048 + d4 * 4);
        acc.x += w0 * v.x; acc.y += w0 * v.y; acc.z += w0 * v.z; acc.w += w0 * v.w;
      }
      if (i1 >= 0) {
        float4 v = *(const float4*)(imgf + (size_t)i1 * 2048 + d4 * 4);
        acc.x += w1 * v.x; acc.y += w1 * v.y; acc.z += w1 * v.z; acc.w += w1 * v.w;
      }
      if (i2 >= 0) {
        float4 v = *(const float4*)(imgf + (size_t)i2 * 2048 + d4 * 4);
        acc.x += w2 * v.x; acc.y += w2 * v.y; acc.z += w2 * v.z; acc.w += w2 * v.w;
      }
    } else if (d4 == 512) {
      acc = make_float4(lb, lb, lb, lb);
      if (i0 >= 0) {
        float4 v = *(const float4*)(bbox + i0 * 4);
        acc.x += w0 * v.x; acc.y += w0 * v.y; acc.z += w0 * v.z; acc.w += w0 * v.w;
      }
      if (i1 >= 0) {
        float4 v = *(const float4*)(bbox + i1 * 4);
        acc.x += w1 * v.x; acc.y += w1 * v.y; acc.z += w1 * v.z; acc.w += w1 * v.w;
      }
      if (i2 >= 0) {
        float4 v = *(const float4*)(bbox + i2 * 4);
        acc.x += w2 * v.x; acc.y += w2 * v.y; acc.z += w2 * v.z; acc.w += w2 * v.w;
      }
    }
    uint2 hv;
    hv.x = packh2(__float2half(acc.x), __float2half(acc.y));
    hv.y = packh2(__float2half(acc.z), __float2half(acc.w));
    *(uint2*)(hrow + d4 * 4) = hv;
  }
}

// ---------------------------------------------------------------------------
// K1b (fused prep): wconv (blocks 0..4223) + adjconv (4224..7807) +
// zeropad (7808..9343), branch by block range.
// ---------------------------------------------------------------------------
#define WCONV_BLKS (64 * 66)            // (OUT_/32) x (KP_/32)
#define ADJC_BLKS  ((B_ * 128 * CPAD_) / 256)   // 3584
#define ZP_BLKS    ((B_ * 12 * OUT_ / 4) / 256) // 1536
#define PREP_BLKS  (WCONV_BLKS + ADJC_BLKS + ZP_BLKS)

__global__ __launch_bounds__(256) void prep_kernel(
    const float* __restrict__ W, const float* __restrict__ adj,
    const float* __restrict__ X) {
  int blk = blockIdx.x;
  if (blk < WCONV_BLKS) {
    __shared__ float tile[32][33];
    int n0 = (blk % 64) * 32, k0 = (blk / 64) * 32;
    int tx = threadIdx.x & 31, ty = threadIdx.x >> 5;
    for (int i = ty; i < 32; i += 8) {
      int k = k0 + i;
      tile[i][tx] = (k < FEAT_) ? W[(size_t)k * OUT_ + n0 + tx] : 0.f;
    }
    __syncthreads();
    for (int i = ty; i < 32; i += 8) {
      int n = n0 + i;
      g_W[(size_t)n * KP_ + k0 + tx] = __float2half(tile[tx][i]);
    }
  } else if (blk < WCONV_BLKS + ADJC_BLKS) {
    int idx = (blk - WCONV_BLKS) * 256 + threadIdx.x;
    int b = idx / (128 * CPAD_);
    int rem = idx % (128 * CPAD_);
    int c = rem / CPAD_, n = rem % CPAD_;
    float v = 0.f;
    if (c < C_ && n < C_) v = X[c * C_ + n] + adj[(size_t)b * C_ * C_ + c * C_ + n];
    __half hi = __float2half(v);
    __half lo = __float2half(v - __half2float(hi));
    g_adjh[idx] = hi;
    g_adjl[idx] = lo;
  } else {
    int i4 = (blk - WCONV_BLKS - ADJC_BLKS) * 256 + threadIdx.x;
    int off = i4 * 4;
    int b = off / (12 * OUT_);
    int rem = off % (12 * OUT_);
    int pr = rem / OUT_, o = rem % OUT_;
    size_t row = (size_t)b * CPAD_ + 100 + pr;
    *(uint2*)(g_S + row * OUT_ + o) = make_uint2(0u, 0u);
  }
}

// ---------------------------------------------------------------------------
// K2: support = x @ gc_w via mma.sync fp16.
// CTA 128x256, BK=32, 8 warps (warp tile 64x64), 3-stage cp.async pipeline,
// single-sync mainloop, register double-buffered fragments (both k-steps
// loaded before MMAs so LDSM latency is covered by LDSM issue).
// SW64 swizzle u' = u ^ ((r>>1)&3).
// ---------------------------------------------------------------------------
#define ATILE_B  8192                   // 128*32*2
#define WTILE_B  16384                  // 256*32*2
#define BUF_B    (ATILE_B + WTILE_B)    // 24576
#define NSTAGE   3
#define GEMM_SMEM (NSTAGE * BUF_B)      // 73728

__device__ __forceinline__ void load_chunk(uint32_t sb, int buf, int bm, int bn, int k0) {
  int tid = threadIdx.x;
  uint32_t base = sb + buf * BUF_B;
#pragma unroll
  for (int h = 0; h < 2; h++) {
    int idx = tid + h * 256;            // 0..511: 128 rows x 4 units
    int r = idx >> 2, u = idx & 3;
    uint32_t sw = (uint32_t)(r * 64 + ((u ^ ((r >> 1) & 3)) * 16));
    cp_async16(base + sw, g_A + (size_t)(bm + r) * KP_ + k0 + u * 8);
  }
#pragma unroll
  for (int h = 0; h < 4; h++) {
    int idx = tid + h * 256;            // 0..1023: 256 rows x 4 units
    int r = idx >> 2, u = idx & 3;
    uint32_t sw = (uint32_t)(r * 64 + ((u ^ ((r >> 1) & 3)) * 16));
    cp_async16(base + ATILE_B + sw, g_W + (size_t)(bn + r) * KP_ + k0 + u * 8);
  }
  asm volatile("cp.async.commit_group;" ::: "memory");
}

__global__ __launch_bounds__(256, 1) void gemm_kernel() {
  extern __shared__ __align__(128) char smem[];
  uint32_t sb = smem_u32(smem);
  int tid = threadIdx.x;
  int l = tid & 31, w = tid >> 5;
  int wm = w >> 2, wn = w & 3;          // 2 x 4 warp grid, warp tile 64x64
  int bm = blockIdx.y * 128, bn = blockIdx.x * 256;

  float acc[4][8][4];
#pragma unroll
  for (int i = 0; i < 4; i++)
#pragma unroll
    for (int j = 0; j < 8; j++)
#pragma unroll
      for (int k = 0; k < 4; k++) acc[i][j][k] = 0.f;

  uint32_t a_off[2], b_off[2];
#pragma unroll
  for (int ks = 0; ks < 2; ks++) {
    {
      int r = wm * 64 + (l & 15);
      int u = ks * 2 + (l >> 4);
      a_off[ks] = (uint32_t)(r * 64 + ((u ^ ((r >> 1) & 3)) * 16));
    }
    {
      int n = wn * 64 + (l & 7) + ((l >> 4) << 3);
      int u = ks * 2 + ((l >> 3) & 1);
      b_off[ks] = (uint32_t)(n * 64 + ((u ^ ((n >> 1) & 3)) * 16));
    }
  }

  load_chunk(sb, 0, bm, bn, 0);
  load_chunk(sb, 1, bm, bn, 32);
  for (int c = 0; c < NCH_; c++) {
    if (c + 1 < NCH_) {
      asm volatile("cp.async.wait_group 1;" ::: "memory");
    } else {
      asm volatile("cp.async.wait_group 0;" ::: "memory");
    }
    __syncthreads();
    if (c + 2 < NCH_) load_chunk(sb, (c + 2) % NSTAGE, bm, bn, (c + 2) * 32);

    uint32_t base = sb + (c % NSTAGE) * BUF_B;
    // Load ALL fragments for both k-steps first (16 LDSM back-to-back),
    // then run all 64 HMMA — later LDSM issue covers earlier LDSM latency.
    uint32_t af[2][4][4], bf[2][8][2];
#pragma unroll
    for (int ks = 0; ks < 2; ks++) {
#pragma unroll
      for (int mf = 0; mf < 4; mf++) ldm4(af[ks][mf], base + a_off[ks] + mf * 1024);
#pragma unroll
      for (int nf2 = 0; nf2 < 4; nf2++) {
        uint32_t r4[4];
        ldm4(r4, base + ATILE_B + b_off[ks] + nf2 * 1024);
        bf[ks][nf2 * 2][0] = r4[0]; bf[ks][nf2 * 2][1] = r4[1];
        bf[ks][nf2 * 2 + 1][0] = r4[2]; bf[ks][nf2 * 2 + 1][1] = r4[3];
      }
    }
#pragma unroll
    for (int ks = 0; ks < 2; ks++)
#pragma unroll
      for (int mf = 0; mf < 4; mf++)
#pragma unroll
        for (int nf = 0; nf < 8; nf++) mma_f16(acc[mf][nf], af[ks][mf], bf[ks][nf]);
  }

  // epilogue: single fp16 plane, store at remapped rows b*112 + c
  int rl = l >> 2, cl = (l & 3) * 2;
#pragma unroll
  for (int mf = 0; mf < 4; mf++) {
    int r0 = bm + wm * 64 + mf * 16 + rl;
    int r1 = r0 + 8;
    int s0 = (r0 / 100) * CPAD_ + (r0 % 100);
    int s1 = (r1 / 100) * CPAD_ + (r1 % 100);
#pragma unroll
    for (int nf = 0; nf < 8; nf++) {
      int cg = bn + wn * 64 + nf * 8 + cl;
      *(uint32_t*)(g_S + (size_t)s0 * OUT_ + cg) =
          packh2(__float2half(acc[mf][nf][0]), __float2half(acc[mf][nf][1]));
      *(uint32_t*)(g_S + (size_t)s1 * OUT_ + cg) =
          packh2(__float2half(acc[mf][nf][2]), __float2half(acc[mf][nf][3]));
    }
  }
}

// ---------------------------------------------------------------------------
// K3: tensor-core adj GEMM + leaky_relu + attention reduce (unchanged).
// ---------------------------------------------------------------------------
#define K3_AH   0
#define K3_AL   30720
#define K3_B    61440
#define K3_G    120576
#define K3_RED  121088
#define K3_SMEM 123136

__global__ __launch_bounds__(256, 1) void adj_att_tc(
    const float* __restrict__ gfeat, const float* __restrict__ gc_b,
    float* __restrict__ out) {
  extern __shared__ __align__(128) char smem[];
  uint32_t sb = smem_u32(smem);
  int b = blockIdx.y;
  int on = blockIdx.x * 256;
  int tid = threadIdx.x;
  int l = tid & 31, w = tid >> 5;
  int wm = w >> 2, wn = w & 3;

  float* Gs = (float*)(smem + K3_G);
  if (tid < 128) Gs[tid] = (tid < C_) ? gfeat[b * C_ + tid] : 0.f;

#pragma unroll
  for (int h = 0; h < 7; h++) {
    int idx = tid + h * 256;            // 0..1791: 128 rows x 14 units
    int r = idx / 14, u = idx % 14;
    uint32_t sw = (uint32_t)(r * 240 + u * 16);
    size_t goff = ((size_t)(b * 128 + r)) * CPAD_ + u * 8;
    cp_async16(sb + K3_AH + sw, g_adjh + goff);
    cp_async16(sb + K3_AL + sw, g_adjl + goff);
  }
#pragma unroll
  for (int h = 0; h < 14; h++) {
    int idx = tid + h * 256;            // 0..3583: 112 rows x 32 units
    int r = idx >> 5, u = idx & 31;
    uint32_t sw = (uint32_t)(r * 528 + u * 16);
    cp_async16(sb + K3_B + sw, g_S + ((size_t)(b * CPAD_ + r)) * OUT_ + on + u * 8);
  }
  asm volatile("cp.async.commit_group;" ::: "memory");
  asm volatile("cp.async.wait_group 0;" ::: "memory");
  __syncthreads();

  float acc[4][8][4];
#pragma unroll
  for (int i = 0; i < 4; i++)
#pragma unroll
    for (int j = 0; j < 8; j++)
#pragma unroll
      for (int k = 0; k < 4; k++) acc[i][j][k] = 0.f;

  int arow = wm * 64 + (l & 15);
  int krow_b = (l & 7) + (((l >> 3) & 1) << 3);
  uint32_t ncol_b = (uint32_t)((wn * 64 + ((l >> 4) << 3)) * 2);

#pragma unroll
  for (int kt = 0; kt < 7; kt++) {
    int k0 = kt * 16;
    uint32_t ah[4][4], al[4][4], bf[8][2];
    uint32_t abase = sb + (uint32_t)(arow * 240 + k0 * 2 + ((l >> 4) << 4));
#pragma unroll
    for (int mf = 0; mf < 4; mf++) {
      ldm4(ah[mf], abase + K3_AH + mf * (16 * 240));
      ldm4(al[mf], abase + K3_AL + mf * (16 * 240));
    }
    uint32_t bbase = sb + K3_B + (uint32_t)((k0 + krow_b) * 528) + ncol_b;
#pragma unroll
    for (int nf2 = 0; nf2 < 4; nf2++) {
      uint32_t r4[4];
      ldm4t(r4, bbase + nf2 * 32);
      bf[nf2 * 2][0] = r4[0]; bf[nf2 * 2][1] = r4[1];
      bf[nf2 * 2 + 1][0] = r4[2]; bf[nf2 * 2 + 1][1] = r4[3];
    }
#pragma unroll
    for (int mf = 0; mf < 4; mf++)
#pragma unroll
      for (int nf = 0; nf < 8; nf++) {
        mma_f16(acc[mf][nf], ah[mf], bf[nf]);
        mma_f16(acc[mf][nf], al[mf], bf[nf]);
      }
  }

  // epilogue: bias + leaky_relu + g-weighted reduction over c
  int rl = l >> 2, cl = (l & 3) * 2;
  float part[8][2];
#pragma unroll
  for (int nf = 0; nf < 8; nf++) { part[nf][0] = 0.f; part[nf][1] = 0.f; }
#pragma unroll
  for (int mf = 0; mf < 4; mf++) {
    int c0 = wm * 64 + mf * 16 + rl;
    float g0 = Gs[c0], g1 = Gs[c0 + 8];
#pragma unroll
    for (int nf = 0; nf < 8; nf++) {
      int o = wn * 64 + nf * 8 + cl;
      float2 bias = *(const float2*)(gc_b + on + o);
      float s00 = acc[mf][nf][0] + bias.x;
      float s01 = acc[mf][nf][1] + bias.y;
      float s10 = acc[mf][nf][2] + bias.x;
      float s11 = acc[mf][nf][3] + bias.y;
      s00 = (s00 > 0.f) ? s00 : 0.01f * s00;
      s01 = (s01 > 0.f) ? s01 : 0.01f * s01;
      s10 = (s10 > 0.f) ? s10 : 0.01f * s10;
      s11 = (s11 > 0.f) ? s11 : 0.01f * s11;
      part[nf][0] += g0 * s00 + g1 * s10;
      part[nf][1] += g0 * s01 + g1 * s11;
    }
  }
#pragma unroll
  for (int off = 4; off < 32; off <<= 1)
#pragma unroll
    for (int nf = 0; nf < 8; nf++) {
      part[nf][0] += __shfl_xor_sync(0xffffffffu, part[nf][0], off);
      part[nf][1] += __shfl_xor_sync(0xffffffffu, part[nf][1], off);
    }
  float* red = (float*)(smem + K3_RED);
  if (l < 4) {
#pragma unroll
    for (int nf = 0; nf < 8; nf++) {
      int o = wn * 64 + nf * 8 + l * 2;
      red[wm * 256 + o] = part[nf][0];
      red[wm * 256 + o + 1] = part[nf][1];
    }
  }
  __syncthreads();
  {
    float s = red[tid] + red[256 + tid];
    out[(size_t)b * OUT_ + on + tid] = s;
  }
}

// ---------------------------------------------------------------------------
extern "C" void kernel_launch(void* const* d_in, const int* in_sizes, int n_in,
                              void* d_out, int out_size) {
  const float* imgf  = (const float*)d_in[0];
  const float* bbox  = (const float*)d_in[1];
  const float* gfeat = (const float*)d_in[2];
  const float* adj   = (const float*)d_in[3];
  const float* X     = (const float*)d_in[4];
  const float* lin_w = (const float*)d_in[5];
  const float* lin_b = (const float*)d_in[6];
  const float* gc_w  = (const float*)d_in[7];
  const float* gc_b  = (const float*)d_in[8];
  const int*   label = (const int*)d_in[9];
  const int*   batch = (const int*)d_in[10];
  float* out = (float*)d_out;

  cudaFuncSetAttribute(gemm_kernel, cudaFuncAttributeMaxDynamicSharedMemorySize, GEMM_SMEM);
  cudaFuncSetAttribute(adj_att_tc, cudaFuncAttributeMaxDynamicSharedMemorySize, K3_SMEM);

  build_x_kernel<<<M_, 256>>>(imgf, bbox, label, batch, lin_w, lin_b);
  prep_kernel<<<PREP_BLKS, 256>>>(gc_w, adj, X);

  gemm_kernel<<<dim3(OUT_ / 256, M_ / 128), 256, GEMM_SMEM>>>();

  adj_att_tc<<<dim3(OUT_ / 256, B_), 256, K3_SMEM>>>(gfeat, gc_b, out);
}

// round 11
// speedup vs baseline: 1.5373x; 1.5373x over previous
#include <cuda_runtime.h>
#include <cuda_fp16.h>
#include <cstdint>

// Problem constants
#define B_    64
#define C_    100
#define NB_   150
#define FEAT_ 2052
#define OUT_  2048
#define M_    6400          // B_*C_
#define KP_   2112          // GEMM1 K padded
#define NCH_  65            // chunks of BK=32
#define CPAD_ 112           // per-image padded row count for support (K3 k-dim)
#define SROWS (B_ * CPAD_)  // 7168

// Scratch (static device arrays; no runtime allocation allowed)
__device__ __half g_A[(size_t)M_ * KP_];              // x in fp16
__device__ __half g_W[(size_t)OUT_ * KP_];            // K-major: [n][k]
__device__ __half g_S[(size_t)SROWS * OUT_];          // support fp16, rows b*112+c
__device__ __half g_adjh[(size_t)B_ * 128 * CPAD_];   // newadj fp16 [b][c(128)][n(112)]

// ---------------------------------------------------------------------------
__device__ __forceinline__ uint32_t smem_u32(const void* p) {
  uint32_t a;
  asm("{ .reg .u64 t; cvta.to.shared.u64 t, %1; cvt.u32.u64 %0, t; }" : "=r"(a) : "l"(p));
  return a;
}
__device__ __forceinline__ void cp_async16(uint32_t dst, const void* src) {
  asm volatile("cp.async.cg.shared.global [%0], [%1], 16;" :: "r"(dst), "l"(src));
}
__device__ __forceinline__ void ldm4(uint32_t* r, uint32_t addr) {
  asm volatile("ldmatrix.sync.aligned.m8n8.x4.shared.b16 {%0,%1,%2,%3}, [%4];"
               : "=r"(r[0]), "=r"(r[1]), "=r"(r[2]), "=r"(r[3]) : "r"(addr));
}
__device__ __forceinline__ void ldm4t(uint32_t* r, uint32_t addr) {
  asm volatile("ldmatrix.sync.aligned.m8n8.x4.trans.shared.b16 {%0,%1,%2,%3}, [%4];"
               : "=r"(r[0]), "=r"(r[1]), "=r"(r[2]), "=r"(r[3]) : "r"(addr));
}
__device__ __forceinline__ void mma_f16(float* c, const uint32_t* a, const uint32_t* b) {
  asm volatile("mma.sync.aligned.m16n8k16.row.col.f32.f16.f16.f32 "
               "{%0,%1,%2,%3}, {%4,%5,%6,%7}, {%8,%9}, {%0,%1,%2,%3};"
               : "+f"(c[0]), "+f"(c[1]), "+f"(c[2]), "+f"(c[3])
               : "r"(a[0]), "r"(a[1]), "r"(a[2]), "r"(a[3]), "r"(b[0]), "r"(b[1]));
}
__device__ __forceinline__ uint32_t packh2(__half a, __half b) {
  __half2 h = __halves2half2(a, b);
  return *(uint32_t*)&h;
}

// ---------------------------------------------------------------------------
// K1: build x[b,c,:] -> fp16, zero-pad to KP_. Slot search via SMEM labels.
// ---------------------------------------------------------------------------
__global__ __launch_bounds__(256) void build_x_kernel(
    const float* __restrict__ imgf, const float* __restrict__ bbox,
    const int* __restrict__ label, const int* __restrict__ batch,
    const float* __restrict__ lin_w, const float* __restrict__ lin_b) {
  int bc = blockIdx.x;
  int b = bc / C_, c = bc % C_;
  __shared__ int s_lab[NB_];
  __shared__ int s_idx[3];
  __shared__ float s_w[3];
  int t = threadIdx.x;
  if (t < 3) { s_idx[t] = -1; s_w[t] = 0.f; }
  if (t < NB_) {
    int i = b * NB_ + t;
    s_lab[t] = (batch[i] == b) ? label[i] : 0;
  }
  __syncthreads();
  if (t < NB_ && s_lab[t] == c + 1) {
    int slot = 0;
    for (int tp = 0; tp < t; tp++) slot += (s_lab[tp] == c + 1);
    if (slot < 3) { s_idx[slot] = b * NB_ + t; s_w[slot] = lin_w[slot]; }
  }
  __syncthreads();
  float lb = lin_b[0];
  int i0 = s_idx[0], i1 = s_idx[1], i2 = s_idx[2];
  float w0 = s_w[0], w1 = s_w[1], w2 = s_w[2];
  __half* hrow = g_A + (size_t)bc * KP_;
  for (int d4 = t; d4 < KP_ / 4; d4 += 256) {
    float4 acc = make_float4(0.f, 0.f, 0.f, 0.f);
    if (d4 < 512) {
      acc = make_float4(lb, lb, lb, lb);
      if (i0 >= 0) {
        float4 v = *(const float4*)(imgf + (size_t)i0 * 2048 + d4 * 4);
        acc.x += w0 * v.x; acc.y += w0 * v.y; acc.z += w0 * v.z; acc.w += w0 * v.w;
      }
      if (i1 >= 0) {
        float4 v = *(const float4*)(imgf + (size_t)i1 * 2048 + d4 * 4);
        acc.x += w1 * v.x; acc.y += w1 * v.y; acc.z += w1 * v.z; acc.w += w1 * v.w;
      }
      if (i2 >= 0) {
        float4 v = *(const float4*)(imgf + (size_t)i2 * 2048 + d4 * 4);
        acc.x += w2 * v.x; acc.y += w2 * v.y; acc.z += w2 * v.z; acc.w += w2 * v.w;
      }
    } else if (d4 == 512) {
      acc = make_float4(lb, lb, lb, lb);
      if (i0 >= 0) {
        float4 v = *(const float4*)(bbox + i0 * 4);
        acc.x += w0 * v.x; acc.y += w0 * v.y; acc.z += w0 * v.z; acc.w += w0 * v.w;
      }
      if (i1 >= 0) {
        float4 v = *(const float4*)(bbox + i1 * 4);
        acc.x += w1 * v.x; acc.y += w1 * v.y; acc.z += w1 * v.z; acc.w += w1 * v.w;
      }
      if (i2 >= 0) {
        float4 v = *(const float4*)(bbox + i2 * 4);
        acc.x += w2 * v.x; acc.y += w2 * v.y; acc.z += w2 * v.z; acc.w += w2 * v.w;
      }
    }
    uint2 hv;
    hv.x = packh2(__float2half(acc.x), __float2half(acc.y));
    hv.y = packh2(__float2half(acc.z), __float2half(acc.w));
    *(uint2*)(hrow + d4 * 4) = hv;
  }
}

// ---------------------------------------------------------------------------
// K1b (fused prep): wconv + adjconv + zeropad, branch by block range.
// ---------------------------------------------------------------------------
#define WCONV_BLKS (64 * 66)            // (OUT_/32) x (KP_/32)
#define ADJC_BLKS  ((B_ * 128 * CPAD_) / 256)   // 3584
#define ZP_BLKS    ((B_ * 12 * OUT_ / 4) / 256) // 1536
#define PREP_BLKS  (WCONV_BLKS + ADJC_BLKS + ZP_BLKS)

__global__ __launch_bounds__(256) void prep_kernel(
    const float* __restrict__ W, const float* __restrict__ adj,
    const float* __restrict__ X) {
  int blk = blockIdx.x;
  if (blk < WCONV_BLKS) {
    __shared__ float tile[32][33];
    int n0 = (blk % 64) * 32, k0 = (blk / 64) * 32;
    int tx = threadIdx.x & 31, ty = threadIdx.x >> 5;
    for (int i = ty; i < 32; i += 8) {
      int k = k0 + i;
      tile[i][tx] = (k < FEAT_) ? W[(size_t)k * OUT_ + n0 + tx] : 0.f;
    }
    __syncthreads();
    for (int i = ty; i < 32; i += 8) {
      int n = n0 + i;
      g_W[(size_t)n * KP_ + k0 + tx] = __float2half(tile[tx][i]);
    }
  } else if (blk < WCONV_BLKS + ADJC_BLKS) {
    int idx = (blk - WCONV_BLKS) * 256 + threadIdx.x;
    int b = idx / (128 * CPAD_);
    int rem = idx % (128 * CPAD_);
    int c = rem / CPAD_, n = rem % CPAD_;
    float v = 0.f;
    if (c < C_ && n < C_) v = X[c * C_ + n] + adj[(size_t)b * C_ * C_ + c * C_ + n];
    g_adjh[idx] = __float2half(v);
  } else {
    int i4 = (blk - WCONV_BLKS - ADJC_BLKS) * 256 + threadIdx.x;
    int off = i4 * 4;
    int b = off / (12 * OUT_);
    int rem = off % (12 * OUT_);
    int pr = rem / OUT_, o = rem % OUT_;
    size_t row = (size_t)b * CPAD_ + 100 + pr;
    *(uint2*)(g_S + row * OUT_ + o) = make_uint2(0u, 0u);
  }
}

// ---------------------------------------------------------------------------
// K2: support = x @ gc_w via mma.sync fp16 (R9 mainloop — proven optimum).
// CTA 128x256, BK=32, 8 warps (warp tile 64x64), 3-stage cp.async pipeline,
// single-sync. SW64 swizzle u' = u ^ ((r>>1)&3).
// ---------------------------------------------------------------------------
#define ATILE_B  8192                   // 128*32*2
#define WTILE_B  16384                  // 256*32*2
#define BUF_B    (ATILE_B + WTILE_B)    // 24576
#define NSTAGE   3
#define GEMM_SMEM (NSTAGE * BUF_B)      // 73728

__device__ __forceinline__ void load_chunk(uint32_t sb, int buf, int bm, int bn, int k0) {
  int tid = threadIdx.x;
  uint32_t base = sb + buf * BUF_B;
#pragma unroll
  for (int h = 0; h < 2; h++) {
    int idx = tid + h * 256;            // 0..511: 128 rows x 4 units
    int r = idx >> 2, u = idx & 3;
    uint32_t sw = (uint32_t)(r * 64 + ((u ^ ((r >> 1) & 3)) * 16));
    cp_async16(base + sw, g_A + (size_t)(bm + r) * KP_ + k0 + u * 8);
  }
#pragma unroll
  for (int h = 0; h < 4; h++) {
    int idx = tid + h * 256;            // 0..1023: 256 rows x 4 units
    int r = idx >> 2, u = idx & 3;
    uint32_t sw = (uint32_t)(r * 64 + ((u ^ ((r >> 1) & 3)) * 16));
    cp_async16(base + ATILE_B + sw, g_W + (size_t)(bn + r) * KP_ + k0 + u * 8);
  }
  asm volatile("cp.async.commit_group;" ::: "memory");
}

__global__ __launch_bounds__(256, 1) void gemm_kernel() {
  extern __shared__ __align__(128) char smem[];
  uint32_t sb = smem_u32(smem);
  int tid = threadIdx.x;
  int l = tid & 31, w = tid >> 5;
  int wm = w >> 2, wn = w & 3;          // 2 x 4 warp grid, warp tile 64x64
  int bm = blockIdx.y * 128, bn = blockIdx.x * 256;

  float acc[4][8][4];
#pragma unroll
  for (int i = 0; i < 4; i++)
#pragma unroll
    for (int j = 0; j < 8; j++)
#pragma unroll
      for (int k = 0; k < 4; k++) acc[i][j][k] = 0.f;

  uint32_t a_off[2], b_off[2];
#pragma unroll
  for (int ks = 0; ks < 2; ks++) {
    {
      int r = wm * 64 + (l & 15);
      int u = ks * 2 + (l >> 4);
      a_off[ks] = (uint32_t)(r * 64 + ((u ^ ((r >> 1) & 3)) * 16));
    }
    {
      int n = wn * 64 + (l & 7) + ((l >> 4) << 3);
      int u = ks * 2 + ((l >> 3) & 1);
      b_off[ks] = (uint32_t)(n * 64 + ((u ^ ((n >> 1) & 3)) * 16));
    }
  }

  load_chunk(sb, 0, bm, bn, 0);
  load_chunk(sb, 1, bm, bn, 32);
  for (int c = 0; c < NCH_; c++) {
    if (c + 1 < NCH_) {
      asm volatile("cp.async.wait_group 1;" ::: "memory");
    } else {
      asm volatile("cp.async.wait_group 0;" ::: "memory");
    }
    __syncthreads();
    if (c + 2 < NCH_) load_chunk(sb, (c + 2) % NSTAGE, bm, bn, (c + 2) * 32);

    uint32_t base = sb + (c % NSTAGE) * BUF_B;
#pragma unroll
    for (int ks = 0; ks < 2; ks++) {
      uint32_t af[4][4], bf[8][2];
#pragma unroll
      for (int mf = 0; mf < 4; mf++) ldm4(af[mf], base + a_off[ks] + mf * 1024);
#pragma unroll
      for (int nf2 = 0; nf2 < 4; nf2++) {
        uint32_t r4[4];
        ldm4(r4, base + ATILE_B + b_off[ks] + nf2 * 1024);
        bf[nf2 * 2][0] = r4[0]; bf[nf2 * 2][1] = r4[1];
        bf[nf2 * 2 + 1][0] = r4[2]; bf[nf2 * 2 + 1][1] = r4[3];
      }
#pragma unroll
      for (int mf = 0; mf < 4; mf++)
#pragma unroll
        for (int nf = 0; nf < 8; nf++) mma_f16(acc[mf][nf], af[mf], bf[nf]);
    }
  }

  // epilogue: single fp16 plane, store at remapped rows b*112 + c
  int rl = l >> 2, cl = (l & 3) * 2;
#pragma unroll
  for (int mf = 0; mf < 4; mf++) {
    int r0 = bm + wm * 64 + mf * 16 + rl;
    int r1 = r0 + 8;
    int s0 = (r0 / 100) * CPAD_ + (r0 % 100);
    int s1 = (r1 / 100) * CPAD_ + (r1 % 100);
#pragma unroll
    for (int nf = 0; nf < 8; nf++) {
      int cg = bn + wn * 64 + nf * 8 + cl;
      *(uint32_t*)(g_S + (size_t)s0 * OUT_ + cg) =
          packh2(__float2half(acc[mf][nf][0]), __float2half(acc[mf][nf][1]));
      *(uint32_t*)(g_S + (size_t)s1 * OUT_ + cg) =
          packh2(__float2half(acc[mf][nf][2]), __float2half(acc[mf][nf][3]));
    }
  }
}

// ---------------------------------------------------------------------------
// K3: tensor-core adj GEMM + leaky_relu + attention reduce.
// Single adj plane (fp16). 2-stage load pipeline: group0 = adj + B rows 0..55,
// group1 = B rows 56..111; compute kt 0..2 while group1 streams.
// ---------------------------------------------------------------------------
#define K3_A    0                       // 128 rows x 240 B = 30720
#define K3_B    30720                   // 112 rows x 528 B = 59136
#define K3_G    89856                   // 512
#define K3_RED  90368                   // 2048
#define K3_SMEM 92416

__global__ __launch_bounds__(256, 1) void adj_att_tc(
    const float* __restrict__ gfeat, const float* __restrict__ gc_b,
    float* __restrict__ out) {
  extern __shared__ __align__(128) char smem[];
  uint32_t sb = smem_u32(smem);
  int b = blockIdx.y;
  int on = blockIdx.x * 256;
  int tid = threadIdx.x;
  int l = tid & 31, w = tid >> 5;
  int wm = w >> 2, wn = w & 3;

  float* Gs = (float*)(smem + K3_G);
  if (tid < 128) Gs[tid] = (tid < C_) ? gfeat[b * C_ + tid] : 0.f;

  // group 0: adj plane (128 rows x 14 units) + B rows 0..55
#pragma unroll
  for (int h = 0; h < 7; h++) {
    int idx = tid + h * 256;            // 0..1791
    int r = idx / 14, u = idx % 14;
    cp_async16(sb + K3_A + (uint32_t)(r * 240 + u * 16),
               g_adjh + ((size_t)(b * 128 + r)) * CPAD_ + u * 8);
  }
#pragma unroll
  for (int h = 0; h < 7; h++) {
    int idx = tid + h * 256;            // rows 0..55
    int r = idx >> 5, u = idx & 31;
    cp_async16(sb + K3_B + (uint32_t)(r * 528 + u * 16),
               g_S + ((size_t)(b * CPAD_ + r)) * OUT_ + on + u * 8);
  }
  asm volatile("cp.async.commit_group;" ::: "memory");
  // group 1: B rows 56..111
#pragma unroll
  for (int h = 7; h < 14; h++) {
    int idx = tid + h * 256;
    int r = idx >> 5, u = idx & 31;
    cp_async16(sb + K3_B + (uint32_t)(r * 528 + u * 16),
               g_S + ((size_t)(b * CPAD_ + r)) * OUT_ + on + u * 8);
  }
  asm volatile("cp.async.commit_group;" ::: "memory");

  asm volatile("cp.async.wait_group 1;" ::: "memory");
  __syncthreads();

  float acc[4][8][4];
#pragma unroll
  for (int i = 0; i < 4; i++)
#pragma unroll
    for (int j = 0; j < 8; j++)
#pragma unroll
      for (int k = 0; k < 4; k++) acc[i][j][k] = 0.f;

  int arow = wm * 64 + (l & 15);
  int krow_b = (l & 7) + (((l >> 3) & 1) << 3);
  uint32_t ncol_b = (uint32_t)((wn * 64 + ((l >> 4) << 3)) * 2);

#pragma unroll
  for (int kt = 0; kt < 7; kt++) {
    if (kt == 3) {
      asm volatile("cp.async.wait_group 0;" ::: "memory");
      __syncthreads();
    }
    int k0 = kt * 16;
    uint32_t ah[4][4], bf[8][2];
    uint32_t abase = sb + K3_A + (uint32_t)(arow * 240 + k0 * 2 + ((l >> 4) << 4));
#pragma unroll
    for (int mf = 0; mf < 4; mf++) ldm4(ah[mf], abase + mf * (16 * 240));
    uint32_t bbase = sb + K3_B + (uint32_t)((k0 + krow_b) * 528) + ncol_b;
#pragma unroll
    for (int nf2 = 0; nf2 < 4; nf2++) {
      uint32_t r4[4];
      ldm4t(r4, bbase + nf2 * 32);
      bf[nf2 * 2][0] = r4[0]; bf[nf2 * 2][1] = r4[1];
      bf[nf2 * 2 + 1][0] = r4[2]; bf[nf2 * 2 + 1][1] = r4[3];
    }
#pragma unroll
    for (int mf = 0; mf < 4; mf++)
#pragma unroll
      for (int nf = 0; nf < 8; nf++) mma_f16(acc[mf][nf], ah[mf], bf[nf]);
  }

  // epilogue: bias + leaky_relu + g-weighted reduction over c
  int rl = l >> 2, cl = (l & 3) * 2;
  float part[8][2];
#pragma unroll
  for (int nf = 0; nf < 8; nf++) { part[nf][0] = 0.f; part[nf][1] = 0.f; }
#pragma unroll
  for (int mf = 0; mf < 4; mf++) {
    int c0 = wm * 64 + mf * 16 + rl;
    float g0 = Gs[c0], g1 = Gs[c0 + 8];
#pragma unroll
    for (int nf = 0; nf < 8; nf++) {
      int o = wn * 64 + nf * 8 + cl;
      float2 bias = *(const float2*)(gc_b + on + o);
      float s00 = acc[mf][nf][0] + bias.x;
      float s01 = acc[mf][nf][1] + bias.y;
      float s10 = acc[mf][nf][2] + bias.x;
      float s11 = acc[mf][nf][3] + bias.y;
      s00 = (s00 > 0.f) ? s00 : 0.01f * s00;
      s01 = (s01 > 0.f) ? s01 : 0.01f * s01;
      s10 = (s10 > 0.f) ? s10 : 0.01f * s10;
      s11 = (s11 > 0.f) ? s11 : 0.01f * s11;
      part[nf][0] += g0 * s00 + g1 * s10;
      part[nf][1] += g0 * s01 + g1 * s11;
    }
  }
#pragma unroll
  for (int off = 4; off < 32; off <<= 1)
#pragma unroll
    for (int nf = 0; nf < 8; nf++) {
      part[nf][0] += __shfl_xor_sync(0xffffffffu, part[nf][0], off);
      part[nf][1] += __shfl_xor_sync(0xffffffffu, part[nf][1], off);
    }
  float* red = (float*)(smem + K3_RED);
  if (l < 4) {
#pragma unroll
    for (int nf = 0; nf < 8; nf++) {
      int o = wn * 64 + nf * 8 + l * 2;
      red[wm * 256 + o] = part[nf][0];
      red[wm * 256 + o + 1] = part[nf][1];
    }
  }
  __syncthreads();
  {
    float s = red[tid] + red[256 + tid];
    out[(size_t)b * OUT_ + on + tid] = s;
  }
}

// ---------------------------------------------------------------------------
extern "C" void kernel_launch(void* const* d_in, const int* in_sizes, int n_in,
                              void* d_out, int out_size) {
  const float* imgf  = (const float*)d_in[0];
  const float* bbox  = (const float*)d_in[1];
  const float* gfeat = (const float*)d_in[2];
  const float* adj   = (const float*)d_in[3];
  const float* X     = (const float*)d_in[4];
  const float* lin_w = (const float*)d_in[5];
  const float* lin_b = (const float*)d_in[6];
  const float* gc_w  = (const float*)d_in[7];
  const float* gc_b  = (const float*)d_in[8];
  const int*   label = (const int*)d_in[9];
  const int*   batch = (const int*)d_in[10];
  float* out = (float*)d_out;

  cudaFuncSetAttribute(gemm_kernel, cudaFuncAttributeMaxDynamicSharedMemorySize, GEMM_SMEM);
  cudaFuncSetAttribute(adj_att_tc, cudaFuncAttributeMaxDynamicSharedMemorySize, K3_SMEM);

  build_x_kernel<<<M_, 256>>>(imgf, bbox, label, batch, lin_w, lin_b);
  prep_kernel<<<PREP_BLKS, 256>>>(gc_w, adj, X);

  gemm_kernel<<<dim3(OUT_ / 256, M_ / 128), 256, GEMM_SMEM>>>();

  adj_att_tc<<<dim3(OUT_ / 256, B_), 256, K3_SMEM>>>(gfeat, gc_b, out);
}

// round 12
// speedup vs baseline: 1.5782x; 1.0266x over previous
#include <cuda_runtime.h>
#include <cuda_fp16.h>
#include <cstdint>

// Problem constants
#define B_    64
#define C_    100
#define NB_   150
#define FEAT_ 2052
#define OUT_  2048
#define M_    6400          // B_*C_
#define KP_   2112          // GEMM1 K padded
#define NCH_  65            // chunks of BK=32
#define CPAD_ 112           // per-image padded row count for support (K3 k-dim)
#define SROWS (B_ * CPAD_)  // 7168

// Scratch (static device arrays; no runtime allocation allowed)
__device__ __half g_A[(size_t)M_ * KP_];              // x in fp16
__device__ __half g_W[(size_t)OUT_ * KP_];            // K-major: [n][k]
__device__ __half g_S[(size_t)SROWS * OUT_];          // support fp16, rows b*112+c
__device__ __half g_adjh[(size_t)B_ * 128 * CPAD_];   // newadj fp16 [b][c(128)][n(112)]

// ---------------------------------------------------------------------------
__device__ __forceinline__ uint32_t smem_u32(const void* p) {
  uint32_t a;
  asm("{ .reg .u64 t; cvta.to.shared.u64 t, %1; cvt.u32.u64 %0, t; }" : "=r"(a) : "l"(p));
  return a;
}
__device__ __forceinline__ void cp_async16(uint32_t dst, const void* src) {
  asm volatile("cp.async.cg.shared.global [%0], [%1], 16;" :: "r"(dst), "l"(src));
}
__device__ __forceinline__ void ldm4(uint32_t* r, uint32_t addr) {
  asm volatile("ldmatrix.sync.aligned.m8n8.x4.shared.b16 {%0,%1,%2,%3}, [%4];"
               : "=r"(r[0]), "=r"(r[1]), "=r"(r[2]), "=r"(r[3]) : "r"(addr));
}
__device__ __forceinline__ void ldm4t(uint32_t* r, uint32_t addr) {
  asm volatile("ldmatrix.sync.aligned.m8n8.x4.trans.shared.b16 {%0,%1,%2,%3}, [%4];"
               : "=r"(r[0]), "=r"(r[1]), "=r"(r[2]), "=r"(r[3]) : "r"(addr));
}
__device__ __forceinline__ void mma_f16(float* c, const uint32_t* a, const uint32_t* b) {
  asm volatile("mma.sync.aligned.m16n8k16.row.col.f32.f16.f16.f32 "
               "{%0,%1,%2,%3}, {%4,%5,%6,%7}, {%8,%9}, {%0,%1,%2,%3};"
               : "+f"(c[0]), "+f"(c[1]), "+f"(c[2]), "+f"(c[3])
               : "r"(a[0]), "r"(a[1]), "r"(a[2]), "r"(a[3]), "r"(b[0]), "r"(b[1]));
}
__device__ __forceinline__ uint32_t packh2(__half a, __half b) {
  __half2 h = __halves2half2(a, b);
  return *(uint32_t*)&h;
}

// ---------------------------------------------------------------------------
// K1 (fused pre): build_x (blocks 0..6399) + wconv + adjconv + zeropad.
// ---------------------------------------------------------------------------
#define BX_BLKS    M_
#define WCONV_BLKS (64 * 66)            // (OUT_/32) x (KP_/32)
#define ADJC_BLKS  ((B_ * 128 * CPAD_) / 256)   // 3584
#define ZP_BLKS    ((B_ * 12 * OUT_ / 4) / 256) // 1536
#define PRE_BLKS   (BX_BLKS + WCONV_BLKS + ADJC_BLKS + ZP_BLKS)

__global__ __launch_bounds__(256) void pre_kernel(
    const float* __restrict__ imgf, const float* __restrict__ bbox,
    const int* __restrict__ label, const int* __restrict__ batch,
    const float* __restrict__ lin_w, const float* __restrict__ lin_b,
    const float* __restrict__ W, const float* __restrict__ adj,
    const float* __restrict__ X) {
  int blk = blockIdx.x;
  int t = threadIdx.x;
  if (blk < BX_BLKS) {
    int b = blk / C_, c = blk % C_;
    __shared__ int s_lab[NB_];
    __shared__ int s_idx[3];
    __shared__ float s_w[3];
    if (t < 3) { s_idx[t] = -1; s_w[t] = 0.f; }
    if (t < NB_) {
      int i = b * NB_ + t;
      s_lab[t] = (batch[i] == b) ? label[i] : 0;
    }
    __syncthreads();
    if (t < NB_ && s_lab[t] == c + 1) {
      int slot = 0;
      for (int tp = 0; tp < t; tp++) slot += (s_lab[tp] == c + 1);
      if (slot < 3) { s_idx[slot] = b * NB_ + t; s_w[slot] = lin_w[slot]; }
    }
    __syncthreads();
    float lb = lin_b[0];
    int i0 = s_idx[0], i1 = s_idx[1], i2 = s_idx[2];
    float w0 = s_w[0], w1 = s_w[1], w2 = s_w[2];
    __half* hrow = g_A + (size_t)blk * KP_;
    for (int d4 = t; d4 < KP_ / 4; d4 += 256) {
      float4 acc = make_float4(0.f, 0.f, 0.f, 0.f);
      if (d4 < 512) {
        acc = make_float4(lb, lb, lb, lb);
        if (i0 >= 0) {
          float4 v = *(const float4*)(imgf + (size_t)i0 * 2048 + d4 * 4);
          acc.x += w0 * v.x; acc.y += w0 * v.y; acc.z += w0 * v.z; acc.w += w0 * v.w;
        }
        if (i1 >= 0) {
          float4 v = *(const float4*)(imgf + (size_t)i1 * 2048 + d4 * 4);
          acc.x += w1 * v.x; acc.y += w1 * v.y; acc.z += w1 * v.z; acc.w += w1 * v.w;
        }
        if (i2 >= 0) {
          float4 v = *(const float4*)(imgf + (size_t)i2 * 2048 + d4 * 4);
          acc.x += w2 * v.x; acc.y += w2 * v.y; acc.z += w2 * v.z; acc.w += w2 * v.w;
        }
      } else if (d4 == 512) {
        acc = make_float4(lb, lb, lb, lb);
        if (i0 >= 0) {
          float4 v = *(const float4*)(bbox + i0 * 4);
          acc.x += w0 * v.x; acc.y += w0 * v.y; acc.z += w0 * v.z; acc.w += w0 * v.w;
        }
        if (i1 >= 0) {
          float4 v = *(const float4*)(bbox + i1 * 4);
          acc.x += w1 * v.x; acc.y += w1 * v.y; acc.z += w1 * v.z; acc.w += w1 * v.w;
        }
        if (i2 >= 0) {
          float4 v = *(const float4*)(bbox + i2 * 4);
          acc.x += w2 * v.x; acc.y += w2 * v.y; acc.z += w2 * v.z; acc.w += w2 * v.w;
        }
      }
      uint2 hv;
      hv.x = packh2(__float2half(acc.x), __float2half(acc.y));
      hv.y = packh2(__float2half(acc.z), __float2half(acc.w));
      *(uint2*)(hrow + d4 * 4) = hv;
    }
  } else if (blk < BX_BLKS + WCONV_BLKS) {
    int wb = blk - BX_BLKS;
    __shared__ float tile[32][33];
    int n0 = (wb % 64) * 32, k0 = (wb / 64) * 32;
    int tx = t & 31, ty = t >> 5;
    for (int i = ty; i < 32; i += 8) {
      int k = k0 + i;
      tile[i][tx] = (k < FEAT_) ? W[(size_t)k * OUT_ + n0 + tx] : 0.f;
    }
    __syncthreads();
    for (int i = ty; i < 32; i += 8) {
      int n = n0 + i;
      g_W[(size_t)n * KP_ + k0 + tx] = __float2half(tile[tx][i]);
    }
  } else if (blk < BX_BLKS + WCONV_BLKS + ADJC_BLKS) {
    int idx = (blk - BX_BLKS - WCONV_BLKS) * 256 + t;
    int b = idx / (128 * CPAD_);
    int rem = idx % (128 * CPAD_);
    int c = rem / CPAD_, n = rem % CPAD_;
    float v = 0.f;
    if (c < C_ && n < C_) v = X[c * C_ + n] + adj[(size_t)b * C_ * C_ + c * C_ + n];
    g_adjh[idx] = __float2half(v);
  } else {
    int i4 = (blk - BX_BLKS - WCONV_BLKS - ADJC_BLKS) * 256 + t;
    int off = i4 * 4;
    int b = off / (12 * OUT_);
    int rem = off % (12 * OUT_);
    int pr = rem / OUT_, o = rem % OUT_;
    size_t row = (size_t)b * CPAD_ + 100 + pr;
    *(uint2*)(g_S + row * OUT_ + o) = make_uint2(0u, 0u);
  }
}

// ---------------------------------------------------------------------------
// K2: support = x @ gc_w via mma.sync fp16 (R9 mainloop — proven optimum,
// FROZEN). CTA 128x256, BK=32, 8 warps (64x64), 3-stage, single-sync.
// ---------------------------------------------------------------------------
#define ATILE_B  8192                   // 128*32*2
#define WTILE_B  16384                  // 256*32*2
#define BUF_B    (ATILE_B + WTILE_B)    // 24576
#define NSTAGE   3
#define GEMM_SMEM (NSTAGE * BUF_B)      // 73728

__device__ __forceinline__ void load_chunk(uint32_t sb, int buf, int bm, int bn, int k0) {
  int tid = threadIdx.x;
  uint32_t base = sb + buf * BUF_B;
#pragma unroll
  for (int h = 0; h < 2; h++) {
    int idx = tid + h * 256;            // 0..511: 128 rows x 4 units
    int r = idx >> 2, u = idx & 3;
    uint32_t sw = (uint32_t)(r * 64 + ((u ^ ((r >> 1) & 3)) * 16));
    cp_async16(base + sw, g_A + (size_t)(bm + r) * KP_ + k0 + u * 8);
  }
#pragma unroll
  for (int h = 0; h < 4; h++) {
    int idx = tid + h * 256;            // 0..1023: 256 rows x 4 units
    int r = idx >> 2, u = idx & 3;
    uint32_t sw = (uint32_t)(r * 64 + ((u ^ ((r >> 1) & 3)) * 16));
    cp_async16(base + ATILE_B + sw, g_W + (size_t)(bn + r) * KP_ + k0 + u * 8);
  }
  asm volatile("cp.async.commit_group;" ::: "memory");
}

__global__ __launch_bounds__(256, 1) void gemm_kernel() {
  extern __shared__ __align__(128) char smem[];
  uint32_t sb = smem_u32(smem);
  int tid = threadIdx.x;
  int l = tid & 31, w = tid >> 5;
  int wm = w >> 2, wn = w & 3;          // 2 x 4 warp grid, warp tile 64x64
  int bm = blockIdx.y * 128, bn = blockIdx.x * 256;

  float acc[4][8][4];
#pragma unroll
  for (int i = 0; i < 4; i++)
#pragma unroll
    for (int j = 0; j < 8; j++)
#pragma unroll
      for (int k = 0; k < 4; k++) acc[i][j][k] = 0.f;

  uint32_t a_off[2], b_off[2];
#pragma unroll
  for (int ks = 0; ks < 2; ks++) {
    {
      int r = wm * 64 + (l & 15);
      int u = ks * 2 + (l >> 4);
      a_off[ks] = (uint32_t)(r * 64 + ((u ^ ((r >> 1) & 3)) * 16));
    }
    {
      int n = wn * 64 + (l & 7) + ((l >> 4) << 3);
      int u = ks * 2 + ((l >> 3) & 1);
      b_off[ks] = (uint32_t)(n * 64 + ((u ^ ((n >> 1) & 3)) * 16));
    }
  }

  load_chunk(sb, 0, bm, bn, 0);
  load_chunk(sb, 1, bm, bn, 32);
  for (int c = 0; c < NCH_; c++) {
    if (c + 1 < NCH_) {
      asm volatile("cp.async.wait_group 1;" ::: "memory");
    } else {
      asm volatile("cp.async.wait_group 0;" ::: "memory");
    }
    __syncthreads();
    if (c + 2 < NCH_) load_chunk(sb, (c + 2) % NSTAGE, bm, bn, (c + 2) * 32);

    uint32_t base = sb + (c % NSTAGE) * BUF_B;
#pragma unroll
    for (int ks = 0; ks < 2; ks++) {
      uint32_t af[4][4], bf[8][2];
#pragma unroll
      for (int mf = 0; mf < 4; mf++) ldm4(af[mf], base + a_off[ks] + mf * 1024);
#pragma unroll
      for (int nf2 = 0; nf2 < 4; nf2++) {
        uint32_t r4[4];
        ldm4(r4, base + ATILE_B + b_off[ks] + nf2 * 1024);
        bf[nf2 * 2][0] = r4[0]; bf[nf2 * 2][1] = r4[1];
        bf[nf2 * 2 + 1][0] = r4[2]; bf[nf2 * 2 + 1][1] = r4[3];
      }
#pragma unroll
      for (int mf = 0; mf < 4; mf++)
#pragma unroll
        for (int nf = 0; nf < 8; nf++) mma_f16(acc[mf][nf], af[mf], bf[nf]);
    }
  }

  // epilogue: single fp16 plane, store at remapped rows b*112 + c
  int rl = l >> 2, cl = (l & 3) * 2;
#pragma unroll
  for (int mf = 0; mf < 4; mf++) {
    int r0 = bm + wm * 64 + mf * 16 + rl;
    int r1 = r0 + 8;
    int s0 = (r0 / 100) * CPAD_ + (r0 % 100);
    int s1 = (r1 / 100) * CPAD_ + (r1 % 100);
#pragma unroll
    for (int nf = 0; nf < 8; nf++) {
      int cg = bn + wn * 64 + nf * 8 + cl;
      *(uint32_t*)(g_S + (size_t)s0 * OUT_ + cg) =
          packh2(__float2half(acc[mf][nf][0]), __float2half(acc[mf][nf][1]));
      *(uint32_t*)(g_S + (size_t)s1 * OUT_ + cg) =
          packh2(__float2half(acc[mf][nf][2]), __float2half(acc[mf][nf][3]));
    }
  }
}

// ---------------------------------------------------------------------------
// K3: tensor-core adj GEMM + leaky_relu + attention reduce.
// o-tile 128, grid (16, 64), 8 warps (warp tile 64x32), 2 CTAs/SM
// (launch_bounds 256,2; acc[4][4][4]=64 regs; SMEM 62.7KB).
// 2-stage loads: group0 = adj + B rows 0..63 (kt 0..3), group1 = rows 64..111.
// ---------------------------------------------------------------------------
#define K3_A    0                       // 128 rows x 240 B = 30720
#define K3_BROW 272                     // 128 cols * 2B + 16 pad
#define K3_B    30720                   // 112 rows x 272 B = 30464
#define K3_G    61184                   // 512 B
#define K3_RED  61696                   // 1024 B
#define K3_SMEM 62720

__global__ __launch_bounds__(256, 2) void adj_att_tc(
    const float* __restrict__ gfeat, const float* __restrict__ gc_b,
    float* __restrict__ out) {
  extern __shared__ __align__(128) char smem[];
  uint32_t sb = smem_u32(smem);
  int b = blockIdx.y;
  int on = blockIdx.x * 128;
  int tid = threadIdx.x;
  int l = tid & 31, w = tid >> 5;
  int wm = w >> 2, wn = w & 3;          // 2 x 4: warp tile 64(c) x 32(o)

  float* Gs = (float*)(smem + K3_G);
  if (tid < 128) Gs[tid] = (tid < C_) ? gfeat[b * C_ + tid] : 0.f;

  // group 0: adj plane (128 rows x 14 units) + B rows 0..63 (16 units/row)
#pragma unroll
  for (int h = 0; h < 7; h++) {
    int idx = tid + h * 256;            // 0..1791
    int r = idx / 14, u = idx % 14;
    cp_async16(sb + K3_A + (uint32_t)(r * 240 + u * 16),
               g_adjh + ((size_t)(b * 128 + r)) * CPAD_ + u * 8);
  }
#pragma unroll
  for (int h = 0; h < 4; h++) {
    int idx = tid + h * 256;            // rows 0..63
    int r = idx >> 4, u = idx & 15;
    cp_async16(sb + K3_B + (uint32_t)(r * K3_BROW + u * 16),
               g_S + ((size_t)(b * CPAD_ + r)) * OUT_ + on + u * 8);
  }
  asm volatile("cp.async.commit_group;" ::: "memory");
  // group 1: B rows 64..111
#pragma unroll
  for (int h = 4; h < 7; h++) {
    int idx = tid + h * 256;
    int r = idx >> 4, u = idx & 15;
    cp_async16(sb + K3_B + (uint32_t)(r * K3_BROW + u * 16),
               g_S + ((size_t)(b * CPAD_ + r)) * OUT_ + on + u * 8);
  }
  asm volatile("cp.async.commit_group;" ::: "memory");

  asm volatile("cp.async.wait_group 1;" ::: "memory");
  __syncthreads();

  float acc[4][4][4];
#pragma unroll
  for (int i = 0; i < 4; i++)
#pragma unroll
    for (int j = 0; j < 4; j++)
#pragma unroll
      for (int k = 0; k < 4; k++) acc[i][j][k] = 0.f;

  int arow = wm * 64 + (l & 15);
  int krow_b = (l & 7) + (((l >> 3) & 1) << 3);
  uint32_t ncol_b = (uint32_t)((wn * 32 + ((l >> 4) << 3)) * 2);

#pragma unroll
  for (int kt = 0; kt < 7; kt++) {
    if (kt == 4) {
      asm volatile("cp.async.wait_group 0;" ::: "memory");
      __syncthreads();
    }
    int k0 = kt * 16;
    uint32_t ah[4][4], bf[4][2];
    uint32_t abase = sb + K3_A + (uint32_t)(arow * 240 + k0 * 2 + ((l >> 4) << 4));
#pragma unroll
    for (int mf = 0; mf < 4; mf++) ldm4(ah[mf], abase + mf * (16 * 240));
    uint32_t bbase = sb + K3_B + (uint32_t)((k0 + krow_b) * K3_BROW) + ncol_b;
#pragma unroll
    for (int nf2 = 0; nf2 < 2; nf2++) {
      uint32_t r4[4];
      ldm4t(r4, bbase + nf2 * 32);
      bf[nf2 * 2][0] = r4[0]; bf[nf2 * 2][1] = r4[1];
      bf[nf2 * 2 + 1][0] = r4[2]; bf[nf2 * 2 + 1][1] = r4[3];
    }
#pragma unroll
    for (int mf = 0; mf < 4; mf++)
#pragma unroll
      for (int nf = 0; nf < 4; nf++) mma_f16(acc[mf][nf], ah[mf], bf[nf]);
  }

  // epilogue: bias + leaky_relu + g-weighted reduction over c
  int rl = l >> 2, cl = (l & 3) * 2;
  float part[4][2];
#pragma unroll
  for (int nf = 0; nf < 4; nf++) { part[nf][0] = 0.f; part[nf][1] = 0.f; }
#pragma unroll
  for (int mf = 0; mf < 4; mf++) {
    int c0 = wm * 64 + mf * 16 + rl;
    float g0 = Gs[c0], g1 = Gs[c0 + 8];
#pragma unroll
    for (int nf = 0; nf < 4; nf++) {
      int o = wn * 32 + nf * 8 + cl;
      float2 bias = *(const float2*)(gc_b + on + o);
      float s00 = acc[mf][nf][0] + bias.x;
      float s01 = acc[mf][nf][1] + bias.y;
      float s10 = acc[mf][nf][2] + bias.x;
      float s11 = acc[mf][nf][3] + bias.y;
      s00 = (s00 > 0.f) ? s00 : 0.01f * s00;
      s01 = (s01 > 0.f) ? s01 : 0.01f * s01;
      s10 = (s10 > 0.f) ? s10 : 0.01f * s10;
      s11 = (s11 > 0.f) ? s11 : 0.01f * s11;
      part[nf][0] += g0 * s00 + g1 * s10;
      part[nf][1] += g0 * s01 + g1 * s11;
    }
  }
#pragma unroll
  for (int off = 4; off < 32; off <<= 1)
#pragma unroll
    for (int nf = 0; nf < 4; nf++) {
      part[nf][0] += __shfl_xor_sync(0xffffffffu, part[nf][0], off);
      part[nf][1] += __shfl_xor_sync(0xffffffffu, part[nf][1], off);
    }
  float* red = (float*)(smem + K3_RED);
  if (l < 4) {
#pragma unroll
    for (int nf = 0; nf < 4; nf++) {
      int o = wn * 32 + nf * 8 + l * 2;
      red[wm * 128 + o] = part[nf][0];
      red[wm * 128 + o + 1] = part[nf][1];
    }
  }
  __syncthreads();
  if (tid < 128) {
    out[(size_t)b * OUT_ + on + tid] = red[tid] + red[128 + tid];
  }
}

// ---------------------------------------------------------------------------
extern "C" void kernel_launch(void* const* d_in, const int* in_sizes, int n_in,
                              void* d_out, int out_size) {
  const float* imgf  = (const float*)d_in[0];
  const float* bbox  = (const float*)d_in[1];
  const float* gfeat = (const float*)d_in[2];
  const float* adj   = (const float*)d_in[3];
  const float* X     = (const float*)d_in[4];
  const float* lin_w = (const float*)d_in[5];
  const float* lin_b = (const float*)d_in[6];
  const float* gc_w  = (const float*)d_in[7];
  const float* gc_b  = (const float*)d_in[8];
  const int*   label = (const int*)d_in[9];
  const int*   batch = (const int*)d_in[10];
  float* out = (float*)d_out;

  cudaFuncSetAttribute(gemm_kernel, cudaFuncAttributeMaxDynamicSharedMemorySize, GEMM_SMEM);
  cudaFuncSetAttribute(adj_att_tc, cudaFuncAttributeMaxDynamicSharedMemorySize, K3_SMEM);

  pre_kernel<<<PRE_BLKS, 256>>>(imgf, bbox, label, batch, lin_w, lin_b,
                                gc_w, adj, X);

  gemm_kernel<<<dim3(OUT_ / 256, M_ / 128), 256, GEMM_SMEM>>>();

  adj_att_tc<<<dim3(OUT_ / 128, B_), 256, K3_SMEM>>>(gfeat, gc_b, out);
}

// round 13
// speedup vs baseline: 1.5959x; 1.0112x over previous
#include <cuda_runtime.h>
#include <cuda_fp16.h>
#include <cstdint>

// Problem constants
#define B_    64
#define C_    100
#define NB_   150
#define FEAT_ 2052
#define OUT_  2048
#define M_    6400          // B_*C_
#define KP_   2112          // GEMM1 K padded
#define NCH_  65            // chunks of BK=32
#define CPAD_ 112           // per-image padded row count for support (K3 k-dim)
#define SROWS (B_ * CPAD_)  // 7168

// Scratch (static device arrays; no runtime allocation allowed)
__device__ __half g_A[(size_t)M_ * KP_];              // x in fp16
__device__ __half g_W[(size_t)OUT_ * KP_];            // K-major: [n][k]
__device__ __half g_S[(size_t)SROWS * OUT_];          // support fp16, rows b*112+c
__device__ __half g_adjh[(size_t)B_ * 128 * CPAD_];   // newadj fp16 [b][c(128)][n(112)]

// ---------------------------------------------------------------------------
__device__ __forceinline__ uint32_t smem_u32(const void* p) {
  uint32_t a;
  asm("{ .reg .u64 t; cvta.to.shared.u64 t, %1; cvt.u32.u64 %0, t; }" : "=r"(a) : "l"(p));
  return a;
}
__device__ __forceinline__ void cp_async16(uint32_t dst, const void* src) {
  asm volatile("cp.async.cg.shared.global [%0], [%1], 16;" :: "r"(dst), "l"(src));
}
__device__ __forceinline__ void ldm4(uint32_t* r, uint32_t addr) {
  asm volatile("ldmatrix.sync.aligned.m8n8.x4.shared.b16 {%0,%1,%2,%3}, [%4];"
               : "=r"(r[0]), "=r"(r[1]), "=r"(r[2]), "=r"(r[3]) : "r"(addr));
}
__device__ __forceinline__ void ldm4t(uint32_t* r, uint32_t addr) {
  asm volatile("ldmatrix.sync.aligned.m8n8.x4.trans.shared.b16 {%0,%1,%2,%3}, [%4];"
               : "=r"(r[0]), "=r"(r[1]), "=r"(r[2]), "=r"(r[3]) : "r"(addr));
}
__device__ __forceinline__ void mma_f16(float* c, const uint32_t* a, const uint32_t* b) {
  asm volatile("mma.sync.aligned.m16n8k16.row.col.f32.f16.f16.f32 "
               "{%0,%1,%2,%3}, {%4,%5,%6,%7}, {%8,%9}, {%0,%1,%2,%3};"
               : "+f"(c[0]), "+f"(c[1]), "+f"(c[2]), "+f"(c[3])
               : "r"(a[0]), "r"(a[1]), "r"(a[2]), "r"(a[3]), "r"(b[0]), "r"(b[1]));
}
__device__ __forceinline__ uint32_t packh2(__half a, __half b) {
  __half2 h = __halves2half2(a, b);
  return *(uint32_t*)&h;
}

// ---------------------------------------------------------------------------
// K1 (fused pre): build_x (blocks 0..6399) + wconv + adjconv + zeropad.
// ---------------------------------------------------------------------------
#define BX_BLKS    M_
#define WCONV_BLKS (64 * 33)            // (OUT_/32 n-tiles) x (KP_/64 k-tiles)
#define ADJC_BLKS  ((B_ * 128 * CPAD_) / 256)   // 3584
#define ZP_BLKS    ((B_ * 12 * OUT_ / 4) / 256) // 1536
#define PRE_BLKS   (BX_BLKS + WCONV_BLKS + ADJC_BLKS + ZP_BLKS)

__global__ __launch_bounds__(256) void pre_kernel(
    const float* __restrict__ imgf, const float* __restrict__ bbox,
    const int* __restrict__ label, const int* __restrict__ batch,
    const float* __restrict__ lin_w, const float* __restrict__ lin_b,
    const float* __restrict__ W, const float* __restrict__ adj,
    const float* __restrict__ X) {
  int blk = blockIdx.x;
  int t = threadIdx.x;
  if (blk < BX_BLKS) {
    int b = blk / C_, c = blk % C_;
    __shared__ int s_lab[NB_];
    __shared__ int s_idx[3];
    __shared__ float s_w[3];
    if (t < 3) { s_idx[t] = -1; s_w[t] = 0.f; }
    if (t < NB_) {
      int i = b * NB_ + t;
      s_lab[t] = (batch[i] == b) ? label[i] : 0;
    }
    __syncthreads();
    if (t < NB_ && s_lab[t] == c + 1) {
      int slot = 0;
      for (int tp = 0; tp < t; tp++) slot += (s_lab[tp] == c + 1);
      if (slot < 3) { s_idx[slot] = b * NB_ + t; s_w[slot] = lin_w[slot]; }
    }
    __syncthreads();
    float lb = lin_b[0];
    int i0 = s_idx[0], i1 = s_idx[1], i2 = s_idx[2];
    float w0 = s_w[0], w1 = s_w[1], w2 = s_w[2];
    __half* hrow = g_A + (size_t)blk * KP_;
    for (int d8 = t; d8 < KP_ / 8; d8 += 256) {   // 264 iters of 8 halves
      float4 aA = make_float4(0.f, 0.f, 0.f, 0.f);
      float4 aB = make_float4(0.f, 0.f, 0.f, 0.f);
      if (d8 < 256) {                              // elements d8*8 .. +7 from imgf
        aA = make_float4(lb, lb, lb, lb);
        aB = aA;
        if (i0 >= 0) {
          const float4* p = (const float4*)(imgf + (size_t)i0 * 2048 + d8 * 8);
          float4 v = p[0];
          aA.x += w0 * v.x; aA.y += w0 * v.y; aA.z += w0 * v.z; aA.w += w0 * v.w;
          v = p[1];
          aB.x += w0 * v.x; aB.y += w0 * v.y; aB.z += w0 * v.z; aB.w += w0 * v.w;
        }
        if (i1 >= 0) {
          const float4* p = (const float4*)(imgf + (size_t)i1 * 2048 + d8 * 8);
          float4 v = p[0];
          aA.x += w1 * v.x; aA.y += w1 * v.y; aA.z += w1 * v.z; aA.w += w1 * v.w;
          v = p[1];
          aB.x += w1 * v.x; aB.y += w1 * v.y; aB.z += w1 * v.z; aB.w += w1 * v.w;
        }
        if (i2 >= 0) {
          const float4* p = (const float4*)(imgf + (size_t)i2 * 2048 + d8 * 8);
          float4 v = p[0];
          aA.x += w2 * v.x; aA.y += w2 * v.y; aA.z += w2 * v.z; aA.w += w2 * v.w;
          v = p[1];
          aB.x += w2 * v.x; aB.y += w2 * v.y; aB.z += w2 * v.z; aB.w += w2 * v.w;
        }
      } else if (d8 == 256) {                      // 2048..2051 = bbox; 2052..2055 = 0
        aA = make_float4(lb, lb, lb, lb);
        if (i0 >= 0) {
          float4 v = *(const float4*)(bbox + i0 * 4);
          aA.x += w0 * v.x; aA.y += w0 * v.y; aA.z += w0 * v.z; aA.w += w0 * v.w;
        }
        if (i1 >= 0) {
          float4 v = *(const float4*)(bbox + i1 * 4);
          aA.x += w1 * v.x; aA.y += w1 * v.y; aA.z += w1 * v.z; aA.w += w1 * v.w;
        }
        if (i2 >= 0) {
          float4 v = *(const float4*)(bbox + i2 * 4);
          aA.x += w2 * v.x; aA.y += w2 * v.y; aA.z += w2 * v.z; aA.w += w2 * v.w;
        }
      }
      uint4 hv;
      hv.x = packh2(__float2half(aA.x), __float2half(aA.y));
      hv.y = packh2(__float2half(aA.z), __float2half(aA.w));
      hv.z = packh2(__float2half(aB.x), __float2half(aB.y));
      hv.w = packh2(__float2half(aB.z), __float2half(aB.w));
      *(uint4*)(hrow + d8 * 8) = hv;
    }
  } else if (blk < BX_BLKS + WCONV_BLKS) {
    // wconv: tile 64(k) x 32(n); writes full 128B rows of g_W.
    int wb = blk - BX_BLKS;
    __shared__ float tile[64][33];
    int n0 = (wb & 63) * 32, k0 = (wb >> 6) * 64;
    for (int i = t; i < 64 * 32; i += 256) {
      int kk = i >> 5, nn = i & 31;
      int k = k0 + kk;
      tile[kk][nn] = (k < FEAT_) ? W[(size_t)k * OUT_ + n0 + nn] : 0.f;
    }
    __syncthreads();
    int lane = t & 31, wid = t >> 5;
    for (int nn = wid; nn < 32; nn += 8) {
      int n = n0 + nn;
      uint32_t v = packh2(__float2half(tile[lane * 2][nn]),
                          __float2half(tile[lane * 2 + 1][nn]));
      *(uint32_t*)(g_W + (size_t)n * KP_ + k0 + lane * 2) = v;
    }
  } else if (blk < BX_BLKS + WCONV_BLKS + ADJC_BLKS) {
    int idx = (blk - BX_BLKS - WCONV_BLKS) * 256 + t;
    int b = idx / (128 * CPAD_);
    int rem = idx % (128 * CPAD_);
    int c = rem / CPAD_, n = rem % CPAD_;
    float v = 0.f;
    if (c < C_ && n < C_) v = X[c * C_ + n] + adj[(size_t)b * C_ * C_ + c * C_ + n];
    g_adjh[idx] = __float2half(v);
  } else {
    int i4 = (blk - BX_BLKS - WCONV_BLKS - ADJC_BLKS) * 256 + t;
    int off = i4 * 4;
    int b = off / (12 * OUT_);
    int rem = off % (12 * OUT_);
    int pr = rem / OUT_, o = rem % OUT_;
    size_t row = (size_t)b * CPAD_ + 100 + pr;
    *(uint2*)(g_S + row * OUT_ + o) = make_uint2(0u, 0u);
  }
}

// ---------------------------------------------------------------------------
// K2: support = x @ gc_w via mma.sync fp16 (R9 mainloop — proven optimum,
// FROZEN). CTA 128x256, BK=32, 8 warps (64x64), 3-stage, single-sync.
// ---------------------------------------------------------------------------
#define ATILE_B  8192                   // 128*32*2
#define WTILE_B  16384                  // 256*32*2
#define BUF_B    (ATILE_B + WTILE_B)    // 24576
#define NSTAGE   3
#define GEMM_SMEM (NSTAGE * BUF_B)      // 73728

__device__ __forceinline__ void load_chunk(uint32_t sb, int buf, int bm, int bn, int k0) {
  int tid = threadIdx.x;
  uint32_t base = sb + buf * BUF_B;
#pragma unroll
  for (int h = 0; h < 2; h++) {
    int idx = tid + h * 256;            // 0..511: 128 rows x 4 units
    int r = idx >> 2, u = idx & 3;
    uint32_t sw = (uint32_t)(r * 64 + ((u ^ ((r >> 1) & 3)) * 16));
    cp_async16(base + sw, g_A + (size_t)(bm + r) * KP_ + k0 + u * 8);
  }
#pragma unroll
  for (int h = 0; h < 4; h++) {
    int idx = tid + h * 256;            // 0..1023: 256 rows x 4 units
    int r = idx >> 2, u = idx & 3;
    uint32_t sw = (uint32_t)(r * 64 + ((u ^ ((r >> 1) & 3)) * 16));
    cp_async16(base + ATILE_B + sw, g_W + (size_t)(bn + r) * KP_ + k0 + u * 8);
  }
  asm volatile("cp.async.commit_group;" ::: "memory");
}

__global__ __launch_bounds__(256, 1) void gemm_kernel() {
  extern __shared__ __align__(128) char smem[];
  uint32_t sb = smem_u32(smem);
  int tid = threadIdx.x;
  int l = tid & 31, w = tid >> 5;
  int wm = w >> 2, wn = w & 3;          // 2 x 4 warp grid, warp tile 64x64
  int bm = blockIdx.y * 128, bn = blockIdx.x * 256;

  float acc[4][8][4];
#pragma unroll
  for (int i = 0; i < 4; i++)
#pragma unroll
    for (int j = 0; j < 8; j++)
#pragma unroll
      for (int k = 0; k < 4; k++) acc[i][j][k] = 0.f;

  uint32_t a_off[2], b_off[2];
#pragma unroll
  for (int ks = 0; ks < 2; ks++) {
    {
      int r = wm * 64 + (l & 15);
      int u = ks * 2 + (l >> 4);
      a_off[ks] = (uint32_t)(r * 64 + ((u ^ ((r >> 1) & 3)) * 16));
    }
    {
      int n = wn * 64 + (l & 7) + ((l >> 4) << 3);
      int u = ks * 2 + ((l >> 3) & 1);
      b_off[ks] = (uint32_t)(n * 64 + ((u ^ ((n >> 1) & 3)) * 16));
    }
  }

  load_chunk(sb, 0, bm, bn, 0);
  load_chunk(sb, 1, bm, bn, 32);
  for (int c = 0; c < NCH_; c++) {
    if (c + 1 < NCH_) {
      asm volatile("cp.async.wait_group 1;" ::: "memory");
    } else {
      asm volatile("cp.async.wait_group 0;" ::: "memory");
    }
    __syncthreads();
    if (c + 2 < NCH_) load_chunk(sb, (c + 2) % NSTAGE, bm, bn, (c + 2) * 32);

    uint32_t base = sb + (c % NSTAGE) * BUF_B;
#pragma unroll
    for (int ks = 0; ks < 2; ks++) {
      uint32_t af[4][4], bf[8][2];
#pragma unroll
      for (int mf = 0; mf < 4; mf++) ldm4(af[mf], base + a_off[ks] + mf * 1024);
#pragma unroll
      for (int nf2 = 0; nf2 < 4; nf2++) {
        uint32_t r4[4];
        ldm4(r4, base + ATILE_B + b_off[ks] + nf2 * 1024);
        bf[nf2 * 2][0] = r4[0]; bf[nf2 * 2][1] = r4[1];
        bf[nf2 * 2 + 1][0] = r4[2]; bf[nf2 * 2 + 1][1] = r4[3];
      }
#pragma unroll
      for (int mf = 0; mf < 4; mf++)
#pragma unroll
        for (int nf = 0; nf < 8; nf++) mma_f16(acc[mf][nf], af[mf], bf[nf]);
    }
  }

  // epilogue: single fp16 plane, store at remapped rows b*112 + c
  int rl = l >> 2, cl = (l & 3) * 2;
#pragma unroll
  for (int mf = 0; mf < 4; mf++) {
    int r0 = bm + wm * 64 + mf * 16 + rl;
    int r1 = r0 + 8;
    int s0 = (r0 / 100) * CPAD_ + (r0 % 100);
    int s1 = (r1 / 100) * CPAD_ + (r1 % 100);
#pragma unroll
    for (int nf = 0; nf < 8; nf++) {
      int cg = bn + wn * 64 + nf * 8 + cl;
      *(uint32_t*)(g_S + (size_t)s0 * OUT_ + cg) =
          packh2(__float2half(acc[mf][nf][0]), __float2half(acc[mf][nf][1]));
      *(uint32_t*)(g_S + (size_t)s1 * OUT_ + cg) =
          packh2(__float2half(acc[mf][nf][2]), __float2half(acc[mf][nf][3]));
    }
  }
}

// ---------------------------------------------------------------------------
// K3: tensor-core adj GEMM + leaky_relu + attention reduce.
// o-tile 128, grid (16, 64), 8 warps (warp tile 64x32), 2 CTAs/SM.
// 2-stage loads: group0 = adj + B rows 0..63 (kt 0..3), group1 = rows 64..111.
// ---------------------------------------------------------------------------
#define K3_A    0                       // 128 rows x 240 B = 30720
#define K3_BROW 272                     // 128 cols * 2B + 16 pad
#define K3_B    30720                   // 112 rows x 272 B = 30464
#define K3_G    61184                   // 512 B
#define K3_RED  61696                   // 1024 B
#define K3_SMEM 62720

__global__ __launch_bounds__(256, 2) void adj_att_tc(
    const float* __restrict__ gfeat, const float* __restrict__ gc_b,
    float* __restrict__ out) {
  extern __shared__ __align__(128) char smem[];
  uint32_t sb = smem_u32(smem);
  int b = blockIdx.y;
  int on = blockIdx.x * 128;
  int tid = threadIdx.x;
  int l = tid & 31, w = tid >> 5;
  int wm = w >> 2, wn = w & 3;          // 2 x 4: warp tile 64(c) x 32(o)

  float* Gs = (float*)(smem + K3_G);
  if (tid < 128) Gs[tid] = (tid < C_) ? gfeat[b * C_ + tid] : 0.f;

  // group 0: adj plane (128 rows x 14 units) + B rows 0..63 (16 units/row)
#pragma unroll
  for (int h = 0; h < 7; h++) {
    int idx = tid + h * 256;            // 0..1791
    int r = idx / 14, u = idx % 14;
    cp_async16(sb + K3_A + (uint32_t)(r * 240 + u * 16),
               g_adjh + ((size_t)(b * 128 + r)) * CPAD_ + u * 8);
  }
#pragma unroll
  for (int h = 0; h < 4; h++) {
    int idx = tid + h * 256;            // rows 0..63
    int r = idx >> 4, u = idx & 15;
    cp_async16(sb + K3_B + (uint32_t)(r * K3_BROW + u * 16),
               g_S + ((size_t)(b * CPAD_ + r)) * OUT_ + on + u * 8);
  }
  asm volatile("cp.async.commit_group;" ::: "memory");
  // group 1: B rows 64..111
#pragma unroll
  for (int h = 4; h < 7; h++) {
    int idx = tid + h * 256;
    int r = idx >> 4, u = idx & 15;
    cp_async16(sb + K3_B + (uint32_t)(r * K3_BROW + u * 16),
               g_S + ((size_t)(b * CPAD_ + r)) * OUT_ + on + u * 8);
  }
  asm volatile("cp.async.commit_group;" ::: "memory");

  asm volatile("cp.async.wait_group 1;" ::: "memory");
  __syncthreads();

  float acc[4][4][4];
#pragma unroll
  for (int i = 0; i < 4; i++)
#pragma unroll
    for (int j = 0; j < 4; j++)
#pragma unroll
      for (int k = 0; k < 4; k++) acc[i][j][k] = 0.f;

  int arow = wm * 64 + (l & 15);
  int krow_b = (l & 7) + (((l >> 3) & 1) << 3);
  uint32_t ncol_b = (uint32_t)((wn * 32 + ((l >> 4) << 3)) * 2);

#pragma unroll
  for (int kt = 0; kt < 7; kt++) {
    if (kt == 4) {
      asm volatile("cp.async.wait_group 0;" ::: "memory");
      __syncthreads();
    }
    int k0 = kt * 16;
    uint32_t ah[4][4], bf[4][2];
    uint32_t abase = sb + K3_A + (uint32_t)(arow * 240 + k0 * 2 + ((l >> 4) << 4));
#pragma unroll
    for (int mf = 0; mf < 4; mf++) ldm4(ah[mf], abase + mf * (16 * 240));
    uint32_t bbase = sb + K3_B + (uint32_t)((k0 + krow_b) * K3_BROW) + ncol_b;
#pragma unroll
    for (int nf2 = 0; nf2 < 2; nf2++) {
      uint32_t r4[4];
      ldm4t(r4, bbase + nf2 * 32);
      bf[nf2 * 2][0] = r4[0]; bf[nf2 * 2][1] = r4[1];
      bf[nf2 * 2 + 1][0] = r4[2]; bf[nf2 * 2 + 1][1] = r4[3];
    }
#pragma unroll
    for (int mf = 0; mf < 4; mf++)
#pragma unroll
      for (int nf = 0; nf < 4; nf++) mma_f16(acc[mf][nf], ah[mf], bf[nf]);
  }

  // epilogue: bias + leaky_relu + g-weighted reduction over c
  int rl = l >> 2, cl = (l & 3) * 2;
  float part[4][2];
#pragma unroll
  for (int nf = 0; nf < 4; nf++) { part[nf][0] = 0.f; part[nf][1] = 0.f; }
#pragma unroll
  for (int mf = 0; mf < 4; mf++) {
    int c0 = wm * 64 + mf * 16 + rl;
    float g0 = Gs[c0], g1 = Gs[c0 + 8];
#pragma unroll
    for (int nf = 0; nf < 4; nf++) {
      int o = wn * 32 + nf * 8 + cl;
      float2 bias = *(const float2*)(gc_b + on + o);
      float s00 = acc[mf][nf][0] + bias.x;
      float s01 = acc[mf][nf][1] + bias.y;
      float s10 = acc[mf][nf][2] + bias.x;
      float s11 = acc[mf][nf][3] + bias.y;
      s00 = (s00 > 0.f) ? s00 : 0.01f * s00;
      s01 = (s01 > 0.f) ? s01 : 0.01f * s01;
      s10 = (s10 > 0.f) ? s10 : 0.01f * s10;
      s11 = (s11 > 0.f) ? s11 : 0.01f * s11;
      part[nf][0] += g0 * s00 + g1 * s10;
      part[nf][1] += g0 * s01 + g1 * s11;
    }
  }
#pragma unroll
  for (int off = 4; off < 32; off <<= 1)
#pragma unroll
    for (int nf = 0; nf < 4; nf++) {
      part[nf][0] += __shfl_xor_sync(0xffffffffu, part[nf][0], off);
      part[nf][1] += __shfl_xor_sync(0xffffffffu, part[nf][1], off);
    }
  float* red = (float*)(smem + K3_RED);
  if (l < 4) {
#pragma unroll
    for (int nf = 0; nf < 4; nf++) {
      int o = wn * 32 + nf * 8 + l * 2;
      red[wm * 128 + o] = part[nf][0];
      red[wm * 128 + o + 1] = part[nf][1];
    }
  }
  __syncthreads();
  if (tid < 128) {
    out[(size_t)b * OUT_ + on + tid] = red[tid] + red[128 + tid];
  }
}

// ---------------------------------------------------------------------------
extern "C" void kernel_launch(void* const* d_in, const int* in_sizes, int n_in,
                              void* d_out, int out_size) {
  const float* imgf  = (const float*)d_in[0];
  const float* bbox  = (const float*)d_in[1];
  const float* gfeat = (const float*)d_in[2];
  const float* adj   = (const float*)d_in[3];
  const float* X     = (const float*)d_in[4];
  const float* lin_w = (const float*)d_in[5];
  const float* lin_b = (const float*)d_in[6];
  const float* gc_w  = (const float*)d_in[7];
  const float* gc_b  = (const float*)d_in[8];
  const int*   label = (const int*)d_in[9];
  const int*   batch = (const int*)d_in[10];
  float* out = (float*)d_out;

  cudaFuncSetAttribute(gemm_kernel, cudaFuncAttributeMaxDynamicSharedMemorySize, GEMM_SMEM);
  cudaFuncSetAttribute(adj_att_tc, cudaFuncAttributeMaxDynamicSharedMemorySize, K3_SMEM);

  pre_kernel<<<PRE_BLKS, 256>>>(imgf, bbox, label, batch, lin_w, lin_b,
                                gc_w, adj, X);

  gemm_kernel<<<dim3(OUT_ / 256, M_ / 128), 256, GEMM_SMEM>>>();

  adj_att_tc<<<dim3(OUT_ / 128, B_), 256, K3_SMEM>>>(gfeat, gc_b, out);
}

// round 14
// speedup vs baseline: 1.8036x; 1.1301x over previous
#include <cuda_runtime.h>
#include <cuda_fp16.h>
#include <cstdint>

// Problem constants
#define B_    64
#define C_    100
#define NB_   150
#define FEAT_ 2052
#define OUT_  2048
#define M_    6400          // B_*C_
#define KP_   2112          // GEMM1 K padded
#define NCH_  65            // chunks of BK=32
#define CPAD_ 112           // per-image padded row count for support (K3 k-dim)
#define SROWS (B_ * CPAD_)  // 7168

// Scratch (static device arrays; no runtime allocation allowed)
__device__ __half g_A[(size_t)M_ * KP_];              // x in fp16
__device__ __half g_W[(size_t)OUT_ * KP_];            // K-major: [n][k]
__device__ __half g_S[(size_t)SROWS * OUT_];          // support fp16, rows b*112+c
__device__ __half g_adjh[(size_t)B_ * 128 * CPAD_];   // newadj fp16 [b][c(128)][n(112)]

// ---------------------------------------------------------------------------
__device__ __forceinline__ uint32_t smem_u32(const void* p) {
  uint32_t a;
  asm("{ .reg .u64 t; cvta.to.shared.u64 t, %1; cvt.u32.u64 %0, t; }" : "=r"(a) : "l"(p));
  return a;
}
__device__ __forceinline__ void cp_async16(uint32_t dst, const void* src) {
  asm volatile("cp.async.cg.shared.global [%0], [%1], 16;" :: "r"(dst), "l"(src));
}
__device__ __forceinline__ void ldm4(uint32_t* r, uint32_t addr) {
  asm volatile("ldmatrix.sync.aligned.m8n8.x4.shared.b16 {%0,%1,%2,%3}, [%4];"
               : "=r"(r[0]), "=r"(r[1]), "=r"(r[2]), "=r"(r[3]) : "r"(addr));
}
__device__ __forceinline__ void ldm4t(uint32_t* r, uint32_t addr) {
  asm volatile("ldmatrix.sync.aligned.m8n8.x4.trans.shared.b16 {%0,%1,%2,%3}, [%4];"
               : "=r"(r[0]), "=r"(r[1]), "=r"(r[2]), "=r"(r[3]) : "r"(addr));
}
__device__ __forceinline__ void mma_f16(float* c, const uint32_t* a, const uint32_t* b) {
  asm volatile("mma.sync.aligned.m16n8k16.row.col.f32.f16.f16.f32 "
               "{%0,%1,%2,%3}, {%4,%5,%6,%7}, {%8,%9}, {%0,%1,%2,%3};"
               : "+f"(c[0]), "+f"(c[1]), "+f"(c[2]), "+f"(c[3])
               : "r"(a[0]), "r"(a[1]), "r"(a[2]), "r"(a[3]), "r"(b[0]), "r"(b[1]));
}
__device__ __forceinline__ uint32_t packh2(__half a, __half b) {
  __half2 h = __halves2half2(a, b);
  return *(uint32_t*)&h;
}

// ---------------------------------------------------------------------------
// K1 (fused pre): build_x (blocks 0..6399) + wconv + adjconv + zeropad.
// ---------------------------------------------------------------------------
#define BX_BLKS    M_
#define WCONV_BLKS (64 * 33)            // (OUT_/32 n-tiles) x (KP_/64 k-tiles)
#define ADJC_BLKS  ((B_ * 128 * CPAD_) / 256)   // 3584
#define ZP_BLKS    ((B_ * 12 * OUT_ / 4) / 256) // 1536
#define PRE_BLKS   (BX_BLKS + WCONV_BLKS + ADJC_BLKS + ZP_BLKS)

__global__ __launch_bounds__(256) void pre_kernel(
    const float* __restrict__ imgf, const float* __restrict__ bbox,
    const int* __restrict__ label, const int* __restrict__ batch,
    const float* __restrict__ lin_w, const float* __restrict__ lin_b,
    const float* __restrict__ W, const float* __restrict__ adj,
    const float* __restrict__ X) {
  int blk = blockIdx.x;
  int t = threadIdx.x;
  if (blk < BX_BLKS) {
    int b = blk / C_, c = blk % C_;
    __shared__ int s_lab[NB_];
    __shared__ int s_idx[3];
    __shared__ float s_w[3];
    if (t < 3) { s_idx[t] = -1; s_w[t] = 0.f; }
    if (t < NB_) {
      int i = b * NB_ + t;
      s_lab[t] = (batch[i] == b) ? label[i] : 0;
    }
    __syncthreads();
    if (t < NB_ && s_lab[t] == c + 1) {
      int slot = 0;
      for (int tp = 0; tp < t; tp++) slot += (s_lab[tp] == c + 1);
      if (slot < 3) { s_idx[slot] = b * NB_ + t; s_w[slot] = lin_w[slot]; }
    }
    __syncthreads();
    float lb = lin_b[0];
    int i0 = s_idx[0], i1 = s_idx[1], i2 = s_idx[2];
    float w0 = s_w[0], w1 = s_w[1], w2 = s_w[2];
    __half* hrow = g_A + (size_t)blk * KP_;
    for (int d8 = t; d8 < KP_ / 8; d8 += 256) {   // 264 iters of 8 halves
      float4 aA = make_float4(0.f, 0.f, 0.f, 0.f);
      float4 aB = make_float4(0.f, 0.f, 0.f, 0.f);
      if (d8 < 256) {
        aA = make_float4(lb, lb, lb, lb);
        aB = aA;
        if (i0 >= 0) {
          const float4* p = (const float4*)(imgf + (size_t)i0 * 2048 + d8 * 8);
          float4 v = p[0];
          aA.x += w0 * v.x; aA.y += w0 * v.y; aA.z += w0 * v.z; aA.w += w0 * v.w;
          v = p[1];
          aB.x += w0 * v.x; aB.y += w0 * v.y; aB.z += w0 * v.z; aB.w += w0 * v.w;
        }
        if (i1 >= 0) {
          const float4* p = (const float4*)(imgf + (size_t)i1 * 2048 + d8 * 8);
          float4 v = p[0];
          aA.x += w1 * v.x; aA.y += w1 * v.y; aA.z += w1 * v.z; aA.w += w1 * v.w;
          v = p[1];
          aB.x += w1 * v.x; aB.y += w1 * v.y; aB.z += w1 * v.z; aB.w += w1 * v.w;
        }
        if (i2 >= 0) {
          const float4* p = (const float4*)(imgf + (size_t)i2 * 2048 + d8 * 8);
          float4 v = p[0];
          aA.x += w2 * v.x; aA.y += w2 * v.y; aA.z += w2 * v.z; aA.w += w2 * v.w;
          v = p[1];
          aB.x += w2 * v.x; aB.y += w2 * v.y; aB.z += w2 * v.z; aB.w += w2 * v.w;
        }
      } else if (d8 == 256) {
        aA = make_float4(lb, lb, lb, lb);
        if (i0 >= 0) {
          float4 v = *(const float4*)(bbox + i0 * 4);
          aA.x += w0 * v.x; aA.y += w0 * v.y; aA.z += w0 * v.z; aA.w += w0 * v.w;
        }
        if (i1 >= 0) {
          float4 v = *(const float4*)(bbox + i1 * 4);
          aA.x += w1 * v.x; aA.y += w1 * v.y; aA.z += w1 * v.z; aA.w += w1 * v.w;
        }
        if (i2 >= 0) {
          float4 v = *(const float4*)(bbox + i2 * 4);
          aA.x += w2 * v.x; aA.y += w2 * v.y; aA.z += w2 * v.z; aA.w += w2 * v.w;
        }
      }
      uint4 hv;
      hv.x = packh2(__float2half(aA.x), __float2half(aA.y));
      hv.y = packh2(__float2half(aA.z), __float2half(aA.w));
      hv.z = packh2(__float2half(aB.x), __float2half(aB.y));
      hv.w = packh2(__float2half(aB.z), __float2half(aB.w));
      *(uint4*)(hrow + d8 * 8) = hv;
    }
  } else if (blk < BX_BLKS + WCONV_BLKS) {
    int wb = blk - BX_BLKS;
    __shared__ float tile[64][33];
    int n0 = (wb & 63) * 32, k0 = (wb >> 6) * 64;
    for (int i = t; i < 64 * 32; i += 256) {
      int kk = i >> 5, nn = i & 31;
      int k = k0 + kk;
      tile[kk][nn] = (k < FEAT_) ? W[(size_t)k * OUT_ + n0 + nn] : 0.f;
    }
    __syncthreads();
    int lane = t & 31, wid = t >> 5;
    for (int nn = wid; nn < 32; nn += 8) {
      int n = n0 + nn;
      uint32_t v = packh2(__float2half(tile[lane * 2][nn]),
                          __float2half(tile[lane * 2 + 1][nn]));
      *(uint32_t*)(g_W + (size_t)n * KP_ + k0 + lane * 2) = v;
    }
  } else if (blk < BX_BLKS + WCONV_BLKS + ADJC_BLKS) {
    int idx = (blk - BX_BLKS - WCONV_BLKS) * 256 + t;
    int b = idx / (128 * CPAD_);
    int rem = idx % (128 * CPAD_);
    int c = rem / CPAD_, n = rem % CPAD_;
    float v = 0.f;
    if (c < C_ && n < C_) v = X[c * C_ + n] + adj[(size_t)b * C_ * C_ + c * C_ + n];
    g_adjh[idx] = __float2half(v);
  } else {
    int i4 = (blk - BX_BLKS - WCONV_BLKS - ADJC_BLKS) * 256 + t;
    int off = i4 * 4;
    int b = off / (12 * OUT_);
    int rem = off % (12 * OUT_);
    int pr = rem / OUT_, o = rem % OUT_;
    size_t row = (size_t)b * CPAD_ + 100 + pr;
    *(uint2*)(g_S + row * OUT_ + o) = make_uint2(0u, 0u);
  }
}

// ---------------------------------------------------------------------------
// K2: support = x @ gc_w via mma.sync fp16.
// R3 geometry + R9 pipeline: CTA 128x128, 8 warps (warp tile 64x32),
// BK=32, 3-stage cp.async (48KB), single-sync, 2 CTAs/SM
// (launch_bounds 256,2; acc[4][4][4]=64 regs).
// SW64 swizzle u' = u ^ ((r>>1)&3).
// ---------------------------------------------------------------------------
#define ATILE_B  8192                   // 128*32*2
#define WTILE_B  8192                   // 128*32*2
#define BUF_B    (ATILE_B + WTILE_B)    // 16384
#define NSTAGE   3
#define GEMM_SMEM (NSTAGE * BUF_B)      // 49152

__device__ __forceinline__ void load_chunk(uint32_t sb, int buf, int bm, int bn, int k0) {
  int tid = threadIdx.x;
  uint32_t base = sb + buf * BUF_B;
#pragma unroll
  for (int h = 0; h < 2; h++) {
    int idx = tid + h * 256;            // 0..511: 128 rows x 4 units
    int r = idx >> 2, u = idx & 3;
    uint32_t sw = (uint32_t)(r * 64 + ((u ^ ((r >> 1) & 3)) * 16));
    cp_async16(base + sw, g_A + (size_t)(bm + r) * KP_ + k0 + u * 8);
  }
#pragma unroll
  for (int h = 0; h < 2; h++) {
    int idx = tid + h * 256;            // 0..511: 128 rows x 4 units
    int r = idx >> 2, u = idx & 3;
    uint32_t sw = (uint32_t)(r * 64 + ((u ^ ((r >> 1) & 3)) * 16));
    cp_async16(base + ATILE_B + sw, g_W + (size_t)(bn + r) * KP_ + k0 + u * 8);
  }
  asm volatile("cp.async.commit_group;" ::: "memory");
}

__global__ __launch_bounds__(256, 2) void gemm_kernel() {
  extern __shared__ __align__(128) char smem[];
  uint32_t sb = smem_u32(smem);
  int tid = threadIdx.x;
  int l = tid & 31, w = tid >> 5;
  int wm = w >> 2, wn = w & 3;          // 2(m) x 4(n) warp grid, warp tile 64x32
  int bm = blockIdx.y * 128, bn = blockIdx.x * 128;

  float acc[4][4][4];
#pragma unroll
  for (int i = 0; i < 4; i++)
#pragma unroll
    for (int j = 0; j < 4; j++)
#pragma unroll
      for (int k = 0; k < 4; k++) acc[i][j][k] = 0.f;

  uint32_t a_off[2], b_off[2];
#pragma unroll
  for (int ks = 0; ks < 2; ks++) {
    {
      int r = wm * 64 + (l & 15);
      int u = ks * 2 + (l >> 4);
      a_off[ks] = (uint32_t)(r * 64 + ((u ^ ((r >> 1) & 3)) * 16));
    }
    {
      int n = wn * 32 + (l & 7) + ((l >> 4) << 3);
      int u = ks * 2 + ((l >> 3) & 1);
      b_off[ks] = (uint32_t)(n * 64 + ((u ^ ((n >> 1) & 3)) * 16));
    }
  }

  load_chunk(sb, 0, bm, bn, 0);
  load_chunk(sb, 1, bm, bn, 32);
  for (int c = 0; c < NCH_; c++) {
    if (c + 1 < NCH_) {
      asm volatile("cp.async.wait_group 1;" ::: "memory");
    } else {
      asm volatile("cp.async.wait_group 0;" ::: "memory");
    }
    __syncthreads();
    if (c + 2 < NCH_) load_chunk(sb, (c + 2) % NSTAGE, bm, bn, (c + 2) * 32);

    uint32_t base = sb + (c % NSTAGE) * BUF_B;
#pragma unroll
    for (int ks = 0; ks < 2; ks++) {
      uint32_t af[4][4], bf[4][2];
#pragma unroll
      for (int mf = 0; mf < 4; mf++) ldm4(af[mf], base + a_off[ks] + mf * 1024);
#pragma unroll
      for (int nf2 = 0; nf2 < 2; nf2++) {
        uint32_t r4[4];
        ldm4(r4, base + ATILE_B + b_off[ks] + nf2 * 1024);
        bf[nf2 * 2][0] = r4[0]; bf[nf2 * 2][1] = r4[1];
        bf[nf2 * 2 + 1][0] = r4[2]; bf[nf2 * 2 + 1][1] = r4[3];
      }
#pragma unroll
      for (int mf = 0; mf < 4; mf++)
#pragma unroll
        for (int nf = 0; nf < 4; nf++) mma_f16(acc[mf][nf], af[mf], bf[nf]);
    }
  }

  // epilogue: single fp16 plane, store at remapped rows b*112 + c
  int rl = l >> 2, cl = (l & 3) * 2;
#pragma unroll
  for (int mf = 0; mf < 4; mf++) {
    int r0 = bm + wm * 64 + mf * 16 + rl;
    int r1 = r0 + 8;
    int s0 = (r0 / 100) * CPAD_ + (r0 % 100);
    int s1 = (r1 / 100) * CPAD_ + (r1 % 100);
#pragma unroll
    for (int nf = 0; nf < 4; nf++) {
      int cg = bn + wn * 32 + nf * 8 + cl;
      *(uint32_t*)(g_S + (size_t)s0 * OUT_ + cg) =
          packh2(__float2half(acc[mf][nf][0]), __float2half(acc[mf][nf][1]));
      *(uint32_t*)(g_S + (size_t)s1 * OUT_ + cg) =
          packh2(__float2half(acc[mf][nf][2]), __float2half(acc[mf][nf][3]));
    }
  }
}

// ---------------------------------------------------------------------------
// K3: tensor-core adj GEMM + leaky_relu + attention reduce.
// o-tile 128, grid (16, 64), 8 warps (warp tile 64x32), 2 CTAs/SM.
// 2-stage loads: group0 = adj + B rows 0..63 (kt 0..3), group1 = rows 64..111.
// ---------------------------------------------------------------------------
#define K3_A    0                       // 128 rows x 240 B = 30720
#define K3_BROW 272                     // 128 cols * 2B + 16 pad
#define K3_B    30720                   // 112 rows x 272 B = 30464
#define K3_G    61184                   // 512 B
#define K3_RED  61696                   // 1024 B
#define K3_SMEM 62720

__global__ __launch_bounds__(256, 2) void adj_att_tc(
    const float* __restrict__ gfeat, const float* __restrict__ gc_b,
    float* __restrict__ out) {
  extern __shared__ __align__(128) char smem[];
  uint32_t sb = smem_u32(smem);
  int b = blockIdx.y;
  int on = blockIdx.x * 128;
  int tid = threadIdx.x;
  int l = tid & 31, w = tid >> 5;
  int wm = w >> 2, wn = w & 3;          // 2 x 4: warp tile 64(c) x 32(o)

  float* Gs = (float*)(smem + K3_G);
  if (tid < 128) Gs[tid] = (tid < C_) ? gfeat[b * C_ + tid] : 0.f;

  // group 0: adj plane (128 rows x 14 units) + B rows 0..63 (16 units/row)
#pragma unroll
  for (int h = 0; h < 7; h++) {
    int idx = tid + h * 256;            // 0..1791
    int r = idx / 14, u = idx % 14;
    cp_async16(sb + K3_A + (uint32_t)(r * 240 + u * 16),
               g_adjh + ((size_t)(b * 128 + r)) * CPAD_ + u * 8);
  }
#pragma unroll
  for (int h = 0; h < 4; h++) {
    int idx = tid + h * 256;            // rows 0..63
    int r = idx >> 4, u = idx & 15;
    cp_async16(sb + K3_B + (uint32_t)(r * K3_BROW + u * 16),
               g_S + ((size_t)(b * CPAD_ + r)) * OUT_ + on + u * 8);
  }
  asm volatile("cp.async.commit_group;" ::: "memory");
  // group 1: B rows 64..111
#pragma unroll
  for (int h = 4; h < 7; h++) {
    int idx = tid + h * 256;
    int r = idx >> 4, u = idx & 15;
    cp_async16(sb + K3_B + (uint32_t)(r * K3_BROW + u * 16),
               g_S + ((size_t)(b * CPAD_ + r)) * OUT_ + on + u * 8);
  }
  asm volatile("cp.async.commit_group;" ::: "memory");

  asm volatile("cp.async.wait_group 1;" ::: "memory");
  __syncthreads();

  float acc[4][4][4];
#pragma unroll
  for (int i = 0; i < 4; i++)
#pragma unroll
    for (int j = 0; j < 4; j++)
#pragma unroll
      for (int k = 0; k < 4; k++) acc[i][j][k] = 0.f;

  int arow = wm * 64 + (l & 15);
  int krow_b = (l & 7) + (((l >> 3) & 1) << 3);
  uint32_t ncol_b = (uint32_t)((wn * 32 + ((l >> 4) << 3)) * 2);

#pragma unroll
  for (int kt = 0; kt < 7; kt++) {
    if (kt == 4) {
      asm volatile("cp.async.wait_group 0;" ::: "memory");
      __syncthreads();
    }
    int k0 = kt * 16;
    uint32_t ah[4][4], bf[4][2];
    uint32_t abase = sb + K3_A + (uint32_t)(arow * 240 + k0 * 2 + ((l >> 4) << 4));
#pragma unroll
    for (int mf = 0; mf < 4; mf++) ldm4(ah[mf], abase + mf * (16 * 240));
    uint32_t bbase = sb + K3_B + (uint32_t)((k0 + krow_b) * K3_BROW) + ncol_b;
#pragma unroll
    for (int nf2 = 0; nf2 < 2; nf2++) {
      uint32_t r4[4];
      ldm4t(r4, bbase + nf2 * 32);
      bf[nf2 * 2][0] = r4[0]; bf[nf2 * 2][1] = r4[1];
      bf[nf2 * 2 + 1][0] = r4[2]; bf[nf2 * 2 + 1][1] = r4[3];
    }
#pragma unroll
    for (int mf = 0; mf < 4; mf++)
#pragma unroll
      for (int nf = 0; nf < 4; nf++) mma_f16(acc[mf][nf], ah[mf], bf[nf]);
  }

  // epilogue: bias + leaky_relu + g-weighted reduction over c
  int rl = l >> 2, cl = (l & 3) * 2;
  float part[4][2];
#pragma unroll
  for (int nf = 0; nf < 4; nf++) { part[nf][0] = 0.f; part[nf][1] = 0.f; }
#pragma unroll
  for (int mf = 0; mf < 4; mf++) {
    int c0 = wm * 64 + mf * 16 + rl;
    float g0 = Gs[c0], g1 = Gs[c0 + 8];
#pragma unroll
    for (int nf = 0; nf < 4; nf++) {
      int o = wn * 32 + nf * 8 + cl;
      float2 bias = *(const float2*)(gc_b + on + o);
      float s00 = acc[mf][nf][0] + bias.x;
      float s01 = acc[mf][nf][1] + bias.y;
      float s10 = acc[mf][nf][2] + bias.x;
      float s11 = acc[mf][nf][3] + bias.y;
      s00 = (s00 > 0.f) ? s00 : 0.01f * s00;
      s01 = (s01 > 0.f) ? s01 : 0.01f * s01;
      s10 = (s10 > 0.f) ? s10 : 0.01f * s10;
      s11 = (s11 > 0.f) ? s11 : 0.01f * s11;
      part[nf][0] += g0 * s00 + g1 * s10;
      part[nf][1] += g0 * s01 + g1 * s11;
    }
  }
#pragma unroll
  for (int off = 4; off < 32; off <<= 1)
#pragma unroll
    for (int nf = 0; nf < 4; nf++) {
      part[nf][0] += __shfl_xor_sync(0xffffffffu, part[nf][0], off);
      part[nf][1] += __shfl_xor_sync(0xffffffffu, part[nf][1], off);
    }
  float* red = (float*)(smem + K3_RED);
  if (l < 4) {
#pragma unroll
    for (int nf = 0; nf < 4; nf++) {
      int o = wn * 32 + nf * 8 + l * 2;
      red[wm * 128 + o] = part[nf][0];
      red[wm * 128 + o + 1] = part[nf][1];
    }
  }
  __syncthreads();
  if (tid < 128) {
    out[(size_t)b * OUT_ + on + tid] = red[tid] + red[128 + tid];
  }
}

// ---------------------------------------------------------------------------
extern "C" void kernel_launch(void* const* d_in, const int* in_sizes, int n_in,
                              void* d_out, int out_size) {
  const float* imgf  = (const float*)d_in[0];
  const float* bbox  = (const float*)d_in[1];
  const float* gfeat = (const float*)d_in[2];
  const float* adj   = (const float*)d_in[3];
  const float* X     = (const float*)d_in[4];
  const float* lin_w = (const float*)d_in[5];
  const float* lin_b = (const float*)d_in[6];
  const float* gc_w  = (const float*)d_in[7];
  const float* gc_b  = (const float*)d_in[8];
  const int*   label = (const int*)d_in[9];
  const int*   batch = (const int*)d_in[10];
  float* out = (float*)d_out;

  cudaFuncSetAttribute(gemm_kernel, cudaFuncAttributeMaxDynamicSharedMemorySize, GEMM_SMEM);
  cudaFuncSetAttribute(adj_att_tc, cudaFuncAttributeMaxDynamicSharedMemorySize, K3_SMEM);

  pre_kernel<<<PRE_BLKS, 256>>>(imgf, bbox, label, batch, lin_w, lin_b,
                                gc_w, adj, X);

  gemm_kernel<<<dim3(OUT_ / 128, M_ / 128), 256, GEMM_SMEM>>>();

  adj_att_tc<<<dim3(OUT_ / 128, B_), 256, K3_SMEM>>>(gfeat, gc_b, out);
}

// round 17
// speedup vs baseline: 1.8801x; 1.0424x over previous
#include <cuda_runtime.h>
#include <cuda_fp16.h>
#include <cstdint>

// Problem constants
#define B_    64
#define C_    100
#define NB_   150
#define FEAT_ 2052
#define OUT_  2048
#define M_    6400          // B_*C_
#define KP_   2112          // GEMM1 K padded
#define NCH2_ 33            // chunks of BK=64
#define CPAD_ 112           // per-image padded row count for support (K3 k-dim)
#define SROWS (B_ * CPAD_)  // 7168

// Scratch (static device arrays; no runtime allocation allowed)
__device__ __half g_A[(size_t)M_ * KP_];              // x in fp16
__device__ __half g_W[(size_t)OUT_ * KP_];            // K-major: [n][k]
__device__ __half g_S[(size_t)SROWS * OUT_];          // support fp16, rows b*112+c
__device__ __half g_adjh[(size_t)B_ * 128 * CPAD_];   // newadj fp16 [b][c(128)][n(112)]

// ---------------------------------------------------------------------------
__device__ __forceinline__ uint32_t smem_u32(const void* p) {
  uint32_t a;
  asm("{ .reg .u64 t; cvta.to.shared.u64 t, %1; cvt.u32.u64 %0, t; }" : "=r"(a) : "l"(p));
  return a;
}
__device__ __forceinline__ void cp_async16(uint32_t dst, const void* src) {
  asm volatile("cp.async.cg.shared.global [%0], [%1], 16;" :: "r"(dst), "l"(src));
}
__device__ __forceinline__ void ldm4(uint32_t* r, uint32_t addr) {
  asm volatile("ldmatrix.sync.aligned.m8n8.x4.shared.b16 {%0,%1,%2,%3}, [%4];"
               : "=r"(r[0]), "=r"(r[1]), "=r"(r[2]), "=r"(r[3]) : "r"(addr));
}
__device__ __forceinline__ void ldm4t(uint32_t* r, uint32_t addr) {
  asm volatile("ldmatrix.sync.aligned.m8n8.x4.trans.shared.b16 {%0,%1,%2,%3}, [%4];"
               : "=r"(r[0]), "=r"(r[1]), "=r"(r[2]), "=r"(r[3]) : "r"(addr));
}
__device__ __forceinline__ void mma_f16(float* c, const uint32_t* a, const uint32_t* b) {
  asm volatile("mma.sync.aligned.m16n8k16.row.col.f32.f16.f16.f32 "
               "{%0,%1,%2,%3}, {%4,%5,%6,%7}, {%8,%9}, {%0,%1,%2,%3};"
               : "+f"(c[0]), "+f"(c[1]), "+f"(c[2]), "+f"(c[3])
               : "r"(a[0]), "r"(a[1]), "r"(a[2]), "r"(a[3]), "r"(b[0]), "r"(b[1]));
}
__device__ __forceinline__ uint32_t packh2(__half a, __half b) {
  __half2 h = __halves2half2(a, b);
  return *(uint32_t*)&h;
}

// ---------------------------------------------------------------------------
// K1 (fused pre): build_x (blocks 0..6399) + wconv.
// ---------------------------------------------------------------------------
#define BX_BLKS    M_
#define WCONV_BLKS (64 * 33)            // (OUT_/32 n-tiles) x (KP_/64 k-tiles)
#define PRE_BLKS   (BX_BLKS + WCONV_BLKS)

__global__ __launch_bounds__(256) void pre_kernel(
    const float* __restrict__ imgf, const float* __restrict__ bbox,
    const int* __restrict__ label, const int* __restrict__ batch,
    const float* __restrict__ lin_w, const float* __restrict__ lin_b,
    const float* __restrict__ W) {
  int blk = blockIdx.x;
  int t = threadIdx.x;
  if (blk < BX_BLKS) {
    int b = blk / C_, c = blk % C_;
    __shared__ int s_lab[NB_];
    __shared__ int s_idx[3];
    __shared__ float s_w[3];
    if (t < 3) { s_idx[t] = -1; s_w[t] = 0.f; }
    if (t < NB_) {
      int i = b * NB_ + t;
      s_lab[t] = (batch[i] == b) ? label[i] : 0;
    }
    __syncthreads();
    if (t < NB_ && s_lab[t] == c + 1) {
      int slot = 0;
      for (int tp = 0; tp < t; tp++) slot += (s_lab[tp] == c + 1);
      if (slot < 3) { s_idx[slot] = b * NB_ + t; s_w[slot] = lin_w[slot]; }
    }
    __syncthreads();
    float lb = lin_b[0];
    int i0 = s_idx[0], i1 = s_idx[1], i2 = s_idx[2];
    float w0 = s_w[0], w1 = s_w[1], w2 = s_w[2];
    __half* hrow = g_A + (size_t)blk * KP_;
    for (int d8 = t; d8 < KP_ / 8; d8 += 256) {   // 264 iters of 8 halves
      float4 aA = make_float4(0.f, 0.f, 0.f, 0.f);
      float4 aB = make_float4(0.f, 0.f, 0.f, 0.f);
      if (d8 < 256) {
        aA = make_float4(lb, lb, lb, lb);
        aB = aA;
        if (i0 >= 0) {
          const float4* p = (const float4*)(imgf + (size_t)i0 * 2048 + d8 * 8);
          float4 v = p[0];
          aA.x += w0 * v.x; aA.y += w0 * v.y; aA.z += w0 * v.z; aA.w += w0 * v.w;
          v = p[1];
          aB.x += w0 * v.x; aB.y += w0 * v.y; aB.z += w0 * v.z; aB.w += w0 * v.w;
        }
        if (i1 >= 0) {
          const float4* p = (const float4*)(imgf + (size_t)i1 * 2048 + d8 * 8);
          float4 v = p[0];
          aA.x += w1 * v.x; aA.y += w1 * v.y; aA.z += w1 * v.z; aA.w += w1 * v.w;
          v = p[1];
          aB.x += w1 * v.x; aB.y += w1 * v.y; aB.z += w1 * v.z; aB.w += w1 * v.w;
        }
        if (i2 >= 0) {
          const float4* p = (const float4*)(imgf + (size_t)i2 * 2048 + d8 * 8);
          float4 v = p[0];
          aA.x += w2 * v.x; aA.y += w2 * v.y; aA.z += w2 * v.z; aA.w += w2 * v.w;
          v = p[1];
          aB.x += w2 * v.x; aB.y += w2 * v.y; aB.z += w2 * v.z; aB.w += w2 * v.w;
        }
      } else if (d8 == 256) {
        aA = make_float4(lb, lb, lb, lb);
        if (i0 >= 0) {
          float4 v = *(const float4*)(bbox + i0 * 4);
          aA.x += w0 * v.x; aA.y += w0 * v.y; aA.z += w0 * v.z; aA.w += w0 * v.w;
        }
        if (i1 >= 0) {
          float4 v = *(const float4*)(bbox + i1 * 4);
          aA.x += w1 * v.x; aA.y += w1 * v.y; aA.z += w1 * v.z; aA.w += w1 * v.w;
        }
        if (i2 >= 0) {
          float4 v = *(const float4*)(bbox + i2 * 4);
          aA.x += w2 * v.x; aA.y += w2 * v.y; aA.z += w2 * v.z; aA.w += w2 * v.w;
        }
      }
      uint4 hv;
      hv.x = packh2(__float2half(aA.x), __float2half(aA.y));
      hv.y = packh2(__float2half(aA.z), __float2half(aA.w));
      hv.z = packh2(__float2half(aB.x), __float2half(aB.y));
      hv.w = packh2(__float2half(aB.z), __float2half(aB.w));
      *(uint4*)(hrow + d8 * 8) = hv;
    }
  } else {
    int wb = blk - BX_BLKS;
    __shared__ float tile[64][33];
    int n0 = (wb & 63) * 32, k0 = (wb >> 6) * 64;
    for (int i = t; i < 64 * 32; i += 256) {
      int kk = i >> 5, nn = i & 31;
      int k = k0 + kk;
      tile[kk][nn] = (k < FEAT_) ? W[(size_t)k * OUT_ + n0 + nn] : 0.f;
    }
    __syncthreads();
    int lane = t & 31, wid = t >> 5;
    for (int nn = wid; nn < 32; nn += 8) {
      int n = n0 + nn;
      uint32_t v = packh2(__float2half(tile[lane * 2][nn]),
                          __float2half(tile[lane * 2 + 1][nn]));
      *(uint32_t*)(g_W + (size_t)n * KP_ + k0 + lane * 2) = v;
    }
  }
}

// ---------------------------------------------------------------------------
// K2: support = x @ gc_w via mma.sync fp16.
// CTA 128x128, warp tile 64x32, BK=64, 3-stage (96KB), 2 CTAs/SM,
// single-sync. SW128 swizzle u' = u ^ (r & 7), rows 128B.
// Tail filler blocks (>=800): adjconv + zeropad for K3.
// ---------------------------------------------------------------------------
#define ATILE_B  16384                  // 128*64*2
#define WTILE_B  16384                  // 128*64*2
#define BUF_B    (ATILE_B + WTILE_B)    // 32768
#define NSTAGE   3
#define GEMM_SMEM (NSTAGE * BUF_B)      // 98304

#define GEMM_BLKS  (16 * 50)            // (OUT_/128) x (M_/128) = 800
#define ADJC_BLKS  ((B_ * 128 * CPAD_) / 256)   // 3584
#define ZP_BLKS    ((B_ * 12 * OUT_ / 4) / 256) // 1536
#define K2_BLKS    (GEMM_BLKS + ADJC_BLKS + ZP_BLKS)

__device__ __forceinline__ void load_chunk(uint32_t sb, int buf, int bm, int bn, int k0) {
  int tid = threadIdx.x;
  uint32_t base = sb + buf * BUF_B;
#pragma unroll
  for (int h = 0; h < 4; h++) {
    int idx = tid + h * 256;            // 0..1023: 128 rows x 8 units
    int r = idx >> 3, u = idx & 7;
    uint32_t sw = (uint32_t)(r * 128 + ((u ^ (r & 7)) * 16));
    cp_async16(base + sw, g_A + (size_t)(bm + r) * KP_ + k0 + u * 8);
  }
#pragma unroll
  for (int h = 0; h < 4; h++) {
    int idx = tid + h * 256;
    int r = idx >> 3, u = idx & 7;
    uint32_t sw = (uint32_t)(r * 128 + ((u ^ (r & 7)) * 16));
    cp_async16(base + ATILE_B + sw, g_W + (size_t)(bn + r) * KP_ + k0 + u * 8);
  }
  asm volatile("cp.async.commit_group;" ::: "memory");
}

__global__ __launch_bounds__(256, 2) void gemm_kernel(
    const float* __restrict__ adj, const float* __restrict__ X) {
  int blk = blockIdx.x;
  int tid = threadIdx.x;
  if (blk >= GEMM_BLKS) {
    // ---- filler: adjconv / zeropad (K3 prerequisites) ----
    if (blk < GEMM_BLKS + ADJC_BLKS) {
      int idx = (blk - GEMM_BLKS) * 256 + tid;
      int b = idx / (128 * CPAD_);
      int rem = idx % (128 * CPAD_);
      int c = rem / CPAD_, n = rem % CPAD_;
      float v = 0.f;
      if (c < C_ && n < C_) v = X[c * C_ + n] + adj[(size_t)b * C_ * C_ + c * C_ + n];
      g_adjh[idx] = __float2half(v);
    } else {
      int i4 = (blk - GEMM_BLKS - ADJC_BLKS) * 256 + tid;
      int off = i4 * 4;
      int b = off / (12 * OUT_);
      int rem = off % (12 * OUT_);
      int pr = rem / OUT_, o = rem % OUT_;
      size_t row = (size_t)b * CPAD_ + 100 + pr;
      *(uint2*)(g_S + row * OUT_ + o) = make_uint2(0u, 0u);
    }
    return;
  }

  extern __shared__ __align__(128) char smem[];
  uint32_t sb = smem_u32(smem);
  int l = tid & 31, w = tid >> 5;
  int wm = w >> 2, wn = w & 3;          // 2(m) x 4(n) warp grid, warp tile 64x32
  int bm = (blk >> 4) * 128, bn = (blk & 15) * 128;

  float acc[4][4][4];
#pragma unroll
  for (int i = 0; i < 4; i++)
#pragma unroll
    for (int j = 0; j < 4; j++)
#pragma unroll
      for (int k = 0; k < 4; k++) acc[i][j][k] = 0.f;

  uint32_t a_off[4], b_off[4];
#pragma unroll
  for (int ks = 0; ks < 4; ks++) {
    {
      int r = wm * 64 + (l & 15);
      int u = ks * 2 + (l >> 4);
      a_off[ks] = (uint32_t)(r * 128 + ((u ^ (r & 7)) * 16));
    }
    {
      int n = wn * 32 + (l & 7) + ((l >> 4) << 3);
      int u = ks * 2 + ((l >> 3) & 1);
      b_off[ks] = (uint32_t)(n * 128 + ((u ^ (n & 7)) * 16));
    }
  }

  load_chunk(sb, 0, bm, bn, 0);
  load_chunk(sb, 1, bm, bn, 64);
  for (int c = 0; c < NCH2_; c++) {
    if (c + 1 < NCH2_) {
      asm volatile("cp.async.wait_group 1;" ::: "memory");
    } else {
      asm volatile("cp.async.wait_group 0;" ::: "memory");
    }
    __syncthreads();
    if (c + 2 < NCH2_) load_chunk(sb, (c + 2) % NSTAGE, bm, bn, (c + 2) * 64);

    uint32_t base = sb + (c % NSTAGE) * BUF_B;
#pragma unroll
    for (int ks = 0; ks < 4; ks++) {
      uint32_t af[4][4], bf[4][2];
#pragma unroll
      for (int mf = 0; mf < 4; mf++) ldm4(af[mf], base + a_off[ks] + mf * 2048);
#pragma unroll
      for (int nf2 = 0; nf2 < 2; nf2++) {
        uint32_t r4[4];
        ldm4(r4, base + ATILE_B + b_off[ks] + nf2 * 2048);
        bf[nf2 * 2][0] = r4[0]; bf[nf2 * 2][1] = r4[1];
        bf[nf2 * 2 + 1][0] = r4[2]; bf[nf2 * 2 + 1][1] = r4[3];
      }
#pragma unroll
      for (int mf = 0; mf < 4; mf++)
#pragma unroll
        for (int nf = 0; nf < 4; nf++) mma_f16(acc[mf][nf], af[mf], bf[nf]);
    }
  }

  // epilogue: single fp16 plane, store at remapped rows b*112 + c
  int rl = l >> 2, cl = (l & 3) * 2;
#pragma unroll
  for (int mf = 0; mf < 4; mf++) {
    int r0 = bm + wm * 64 + mf * 16 + rl;
    int r1 = r0 + 8;
    int s0 = (r0 / 100) * CPAD_ + (r0 % 100);
    int s1 = (r1 / 100) * CPAD_ + (r1 % 100);
#pragma unroll
    for (int nf = 0; nf < 4; nf++) {
      int cg = bn + wn * 32 + nf * 8 + cl;
      *(uint32_t*)(g_S + (size_t)s0 * OUT_ + cg) =
          packh2(__float2half(acc[mf][nf][0]), __float2half(acc[mf][nf][1]));
      *(uint32_t*)(g_S + (size_t)s1 * OUT_ + cg) =
          packh2(__float2half(acc[mf][nf][2]), __float2half(acc[mf][nf][3]));
    }
  }
}

// ---------------------------------------------------------------------------
// K3: tensor-core adj GEMM + leaky_relu + attention reduce.
// o-tile 128, grid (16, 64), 8 warps (warp tile 64x32), 2 CTAs/SM.
// 2-stage loads: group0 = adj + B rows 0..63 (kt 0..3), group1 = rows 64..111.
// ---------------------------------------------------------------------------
#define K3_A    0                       // 128 rows x 240 B = 30720
#define K3_BROW 272                     // 128 cols * 2B + 16 pad
#define K3_B    30720                   // 112 rows x 272 B = 30464
#define K3_G    61184                   // 512 B
#define K3_RED  61696                   // 1024 B
#define K3_SMEM 62720

__global__ __launch_bounds__(256, 2) void adj_att_tc(
    const float* __restrict__ gfeat, const float* __restrict__ gc_b,
    float* __restrict__ out) {
  extern __shared__ __align__(128) char smem[];
  uint32_t sb = smem_u32(smem);
  int b = blockIdx.y;
  int on = blockIdx.x * 128;
  int tid = threadIdx.x;
  int l = tid & 31, w = tid >> 5;
  int wm = w >> 2, wn = w & 3;          // 2 x 4: warp tile 64(c) x 32(o)

  float* Gs = (float*)(smem + K3_G);
  if (tid < 128) Gs[tid] = (tid < C_) ? gfeat[b * C_ + tid] : 0.f;

  // group 0: adj plane (128 rows x 14 units) + B rows 0..63 (16 units/row)
#pragma unroll
  for (int h = 0; h < 7; h++) {
    int idx = tid + h * 256;            // 0..1791
    int r = idx / 14, u = idx % 14;
    cp_async16(sb + K3_A + (uint32_t)(r * 240 + u * 16),
               g_adjh + ((size_t)(b * 128 + r)) * CPAD_ + u * 8);
  }
#pragma unroll
  for (int h = 0; h < 4; h++) {
    int idx = tid + h * 256;            // rows 0..63
    int r = idx >> 4, u = idx & 15;
    cp_async16(sb + K3_B + (uint32_t)(r * K3_BROW + u * 16),
               g_S + ((size_t)(b * CPAD_ + r)) * OUT_ + on + u * 8);
  }
  asm volatile("cp.async.commit_group;" ::: "memory");
  // group 1: B rows 64..111
#pragma unroll
  for (int h = 4; h < 7; h++) {
    int idx = tid + h * 256;
    int r = idx >> 4, u = idx & 15;
    cp_async16(sb + K3_B + (uint32_t)(r * K3_BROW + u * 16),
               g_S + ((size_t)(b * CPAD_ + r)) * OUT_ + on + u * 8);
  }
  asm volatile("cp.async.commit_group;" ::: "memory");

  asm volatile("cp.async.wait_group 1;" ::: "memory");
  __syncthreads();

  float acc[4][4][4];
#pragma unroll
  for (int i = 0; i < 4; i++)
#pragma unroll
    for (int j = 0; j < 4; j++)
#pragma unroll
      for (int k = 0; k < 4; k++) acc[i][j][k] = 0.f;

  int arow = wm * 64 + (l & 15);
  int krow_b = (l & 7) + (((l >> 3) & 1) << 3);
  uint32_t ncol_b = (uint32_t)((wn * 32 + ((l >> 4) << 3)) * 2);

#pragma unroll
  for (int kt = 0; kt < 7; kt++) {
    if (kt == 4) {
      asm volatile("cp.async.wait_group 0;" ::: "memory");
      __syncthreads();
    }
    int k0 = kt * 16;
    uint32_t ah[4][4], bf[4][2];
    uint32_t abase = sb + K3_A + (uint32_t)(arow * 240 + k0 * 2 + ((l >> 4) << 4));
#pragma unroll
    for (int mf = 0; mf < 4; mf++) ldm4(ah[mf], abase + mf * (16 * 240));
    uint32_t bbase = sb + K3_B + (uint32_t)((k0 + krow_b) * K3_BROW) + ncol_b;
#pragma unroll
    for (int nf2 = 0; nf2 < 2; nf2++) {
      uint32_t r4[4];
      ldm4t(r4, bbase + nf2 * 32);
      bf[nf2 * 2][0] = r4[0]; bf[nf2 * 2][1] = r4[1];
      bf[nf2 * 2 + 1][0] = r4[2]; bf[nf2 * 2 + 1][1] = r4[3];
    }
#pragma unroll
    for (int mf = 0; mf < 4; mf++)
#pragma unroll
      for (int nf = 0; nf < 4; nf++) mma_f16(acc[mf][nf], ah[mf], bf[nf]);
  }

  // epilogue: bias + leaky_relu + g-weighted reduction over c
  int rl = l >> 2, cl = (l & 3) * 2;
  float part[4][2];
#pragma unroll
  for (int nf = 0; nf < 4; nf++) { part[nf][0] = 0.f; part[nf][1] = 0.f; }
#pragma unroll
  for (int mf = 0; mf < 4; mf++) {
    int c0 = wm * 64 + mf * 16 + rl;
    float g0 = Gs[c0], g1 = Gs[c0 + 8];
#pragma unroll
    for (int nf = 0; nf < 4; nf++) {
      int o = wn * 32 + nf * 8 + cl;
      float2 bias = *(const float2*)(gc_b + on + o);
      float s00 = acc[mf][nf][0] + bias.x;
      float s01 = acc[mf][nf][1] + bias.y;
      float s10 = acc[mf][nf][2] + bias.x;
      float s11 = acc[mf][nf][3] + bias.y;
      s00 = (s00 > 0.f) ? s00 : 0.01f * s00;
      s01 = (s01 > 0.f) ? s01 : 0.01f * s01;
      s10 = (s10 > 0.f) ? s10 : 0.01f * s10;
      s11 = (s11 > 0.f) ? s11 : 0.01f * s11;
      part[nf][0] += g0 * s00 + g1 * s10;
      part[nf][1] += g0 * s01 + g1 * s11;
    }
  }
#pragma unroll
  for (int off = 4; off < 32; off <<= 1)
#pragma unroll
    for (int nf = 0; nf < 4; nf++) {
      part[nf][0] += __shfl_xor_sync(0xffffffffu, part[nf][0], off);
      part[nf][1] += __shfl_xor_sync(0xffffffffu, part[nf][1], off);
    }
  float* red = (float*)(smem + K3_RED);
  if (l < 4) {
#pragma unroll
    for (int nf = 0; nf < 4; nf++) {
      int o = wn * 32 + nf * 8 + l * 2;
      red[wm * 128 + o] = part[nf][0];
      red[wm * 128 + o + 1] = part[nf][1];
    }
  }
  __syncthreads();
  if (tid < 128) {
    out[(size_t)b * OUT_ + on + tid] = red[tid] + red[128 + tid];
  }
}

// ---------------------------------------------------------------------------
extern "C" void kernel_launch(void* const* d_in, const int* in_sizes, int n_in,
                              void* d_out, int out_size) {
  const float* imgf  = (const float*)d_in[0];
  const float* bbox  = (const float*)d_in[1];
  const float* gfeat = (const float*)d_in[2];
  const float* adj   = (const float*)d_in[3];
  const float* X     = (const float*)d_in[4];
  const float* lin_w = (const float*)d_in[5];
  const float* lin_b = (const float*)d_in[6];
  const float* gc_w  = (const float*)d_in[7];
  const float* gc_b  = (const float*)d_in[8];
  const int*   label = (const int*)d_in[9];
  const int*   batch = (const int*)d_in[10];
  float* out = (float*)d_out;

  cudaFuncSetAttribute(gemm_kernel, cudaFuncAttributeMaxDynamicSharedMemorySize, GEMM_SMEM);
  cudaFuncSetAttribute(adj_att_tc, cudaFuncAttributeMaxDynamicSharedMemorySize, K3_SMEM);

  pre_kernel<<<PRE_BLKS, 256>>>(imgf, bbox, label, batch, lin_w, lin_b, gc_w);

  gemm_kernel<<<K2_BLKS, 256, GEMM_SMEM>>>(adj, X);

  adj_att_tc<<<dim3(OUT_ / 128, B_), 256, K3_SMEM>>>(gfeat, gc_b, out);
}